// round 3
// baseline (speedup 1.0000x reference)
#include <cuda_runtime.h>
#include <math.h>

// Problem constants
#define BTOK 4096          // B*T
#define CDIM 1024
#define FFDIM 4096
#define EEXP 8
#define NREXP 6
#define HN 16
#define HSD 64
#define PD 4
#define TLEN 2048

static const size_t M4  = (size_t)BTOK * CDIM;    // 4,194,304
static const size_t M16 = (size_t)BTOK * FFDIM;   // 16,777,216

// ---------------- scratch (static device allocation; no cudaMalloc) -------
// layout (floats):
//  0: xln | 1: r | 2: k | 3: v | 4: w | 5: state | 6: xatt | 7: h
//  8: qbuf | 9: gbuf | 10: obuf   (each M4)
//  then kk, pbuf, kbuf, vbuf (each M16)
//  then small region: cnt(8 int), list(8*4096 int), gate(8*4096 float)
__device__ float g_scratch[11ull * 4194304ull + 4ull * 16777216ull + 131072ull];

// ---------------- generic fp32 tiled GEMM -------------------------------
// C[M,N] = act( gather(A)[M,K] @ B[K,N] ), with optional sparse count,
// row-gather, concat-gather, and scatter-add epilogues.
struct GArgs {
    const float* A;
    const float* A2;     // second half for concat mode
    const float* B;
    float* C;
    int M, N, K, lda, ldb, ldc;
    const int* cnt;      // if non-null, effective M = (*cnt)*cntMul
    int cntMul;
    const int* gidx;     // gather rows for A (gmode 1/2) and scatter rows (epi 5/6)
    int gmode;           // 0 none, 1 gather, 2 concat(A|A2) gather
    int epi;             // 0 plain, 1 sigmoid(acc+bias), 2 relu^2, 3 sigmoid,
                         // 4 tanh, 5 out+=gate*mul*acc (scatter), 6 out+=gate*acc (scatter),
                         // 7 acc+res
    const float* bias;
    const float* res;
    const float* mul;
    const float* gate;
    float* outAdd;
};

__global__ __launch_bounds__(256) void gemm_k(GArgs p) {
    int effM = p.M;
    if (p.cnt) {
        int c = (*p.cnt) * p.cntMul;
        effM = c < p.M ? c : p.M;
    }
    int m0 = blockIdx.y * 64, n0 = blockIdx.x * 64;
    if (m0 >= effM) return;

    __shared__ float As[16][64];
    __shared__ float Bs[16][64];

    int tid = threadIdx.x;
    int aRow = tid >> 2, aCol = (tid & 3) << 2;   // 64 rows x 4 float4-chunks
    int bRow = tid >> 4, bCol = (tid & 15) << 2;  // 16 rows x 16 float4-chunks
    int ty = tid >> 4, tx = tid & 15;

    int gm = m0 + aRow;
    int arow = (p.gmode == 0) ? gm : p.gidx[gm];

    float acc[4][4];
#pragma unroll
    for (int i = 0; i < 4; i++)
#pragma unroll
        for (int j = 0; j < 4; j++) acc[i][j] = 0.f;

    for (int k0 = 0; k0 < p.K; k0 += 16) {
        float4 av;
        if (p.gmode == 2) {
            int col = k0 + aCol;
            const float* src = (col < CDIM)
                ? (p.A  + (size_t)arow * CDIM + col)
                : (p.A2 + (size_t)arow * CDIM + (col - CDIM));
            av = *(const float4*)src;
        } else {
            av = *(const float4*)(p.A + (size_t)arow * p.lda + k0 + aCol);
        }
        As[aCol + 0][aRow] = av.x;
        As[aCol + 1][aRow] = av.y;
        As[aCol + 2][aRow] = av.z;
        As[aCol + 3][aRow] = av.w;

        *(float4*)&Bs[bRow][bCol] =
            *(const float4*)(p.B + (size_t)(k0 + bRow) * p.ldb + n0 + bCol);
        __syncthreads();

#pragma unroll
        for (int kk = 0; kk < 16; kk++) {
            float4 a4 = *(float4*)&As[kk][ty << 2];
            float4 b4 = *(float4*)&Bs[kk][tx << 2];
            float ar[4] = {a4.x, a4.y, a4.z, a4.w};
            float br[4] = {b4.x, b4.y, b4.z, b4.w};
#pragma unroll
            for (int i = 0; i < 4; i++)
#pragma unroll
                for (int j = 0; j < 4; j++) acc[i][j] += ar[i] * br[j];
        }
        __syncthreads();
    }

#pragma unroll
    for (int i = 0; i < 4; i++) {
        int m = m0 + (ty << 2) + i;
        if (m >= effM) continue;
#pragma unroll
        for (int j = 0; j < 4; j++) {
            int n = n0 + (tx << 2) + j;
            float v = acc[i][j];
            switch (p.epi) {
                case 0: p.C[(size_t)m * p.ldc + n] = v; break;
                case 1: p.C[(size_t)m * p.ldc + n] =
                            1.f / (1.f + expf(-(v + p.bias[n]))); break;
                case 2: { float rr = v > 0.f ? v : 0.f;
                          p.C[(size_t)m * p.ldc + n] = rr * rr; } break;
                case 3: p.C[(size_t)m * p.ldc + n] = 1.f / (1.f + expf(-v)); break;
                case 4: p.C[(size_t)m * p.ldc + n] = tanhf(v); break;
                case 5: { int r = p.gidx[m];
                          p.outAdd[(size_t)r * CDIM + n] +=
                              p.gate[m] * p.mul[(size_t)m * CDIM + n] * v; } break;
                case 6: { int r = p.gidx[m];
                          p.outAdd[(size_t)r * CDIM + n] += p.gate[m] * v; } break;
                case 7: p.C[(size_t)m * p.ldc + n] =
                            v + p.res[(size_t)m * p.ldc + n]; break;
            }
        }
    }
}

// ---------------- LayerNorm (one block per row) ---------------------------
__global__ __launch_bounds__(256) void ln_k(const float* __restrict__ x,
                                            const float* __restrict__ w,
                                            const float* __restrict__ b,
                                            float* __restrict__ y) {
    int row = blockIdx.x, tid = threadIdx.x;
    const float* xr = x + (size_t)row * CDIM;
    float v[4], s = 0.f, s2 = 0.f;
#pragma unroll
    for (int i = 0; i < 4; i++) {
        v[i] = xr[tid + 256 * i];
        s += v[i]; s2 += v[i] * v[i];
    }
#pragma unroll
    for (int off = 16; off; off >>= 1) {
        s  += __shfl_xor_sync(0xffffffffu, s, off);
        s2 += __shfl_xor_sync(0xffffffffu, s2, off);
    }
    __shared__ float rs[8], rs2[8];
    int wid = tid >> 5, lane = tid & 31;
    if (lane == 0) { rs[wid] = s; rs2[wid] = s2; }
    __syncthreads();
    if (tid == 0) {
        float S = 0.f, S2 = 0.f;
        for (int i = 0; i < 8; i++) { S += rs[i]; S2 += rs2[i]; }
        rs[0] = S; rs2[0] = S2;
    }
    __syncthreads();
    float mean = rs[0] * (1.f / 1024.f);
    float var  = rs2[0] * (1.f / 1024.f) - mean * mean;
    float inv  = rsqrtf(var + 1e-5f);
#pragma unroll
    for (int i = 0; i < 4; i++) {
        int c = tid + 256 * i;
        y[(size_t)row * CDIM + c] = (v[i] - mean) * inv * w[c] + b[c];
    }
}

// ---------------- RWKV scan: one block per (b,h), state in registers ------
__global__ __launch_bounds__(512) void scan_k(const float* __restrict__ r,
                                              const float* __restrict__ k,
                                              const float* __restrict__ v,
                                              const float* __restrict__ w,
                                              float* __restrict__ y) {
    int bh = blockIdx.x;
    int b = bh >> 4, h = bh & 15;
    int tid = threadIdx.x;
    int vd = tid & 63, kg = tid >> 6;

    __shared__ float rs[64], ks[64], vs[64], ws[64];
    __shared__ float part[8][64];

    float S[8];
#pragma unroll
    for (int i = 0; i < 8; i++) S[i] = 0.f;

    size_t base = (size_t)b * TLEN * CDIM + (size_t)h * HSD;
    for (int t = 0; t < TLEN; t++) {
        size_t off = base + (size_t)t * CDIM;
        if (tid < 256) {
            int which = tid >> 6, j = tid & 63;
            if (which == 0)      rs[j] = r[off + j];
            else if (which == 1) ks[j] = k[off + j];
            else if (which == 2) vs[j] = v[off + j];
            else                 ws[j] = w[off + j];
        }
        __syncthreads();
        float yp = 0.f, vv = vs[vd];
#pragma unroll
        for (int i = 0; i < 8; i++) {
            int ki = kg * 8 + i;
            S[i] = S[i] * ws[ki] + ks[ki] * vv;
            yp += rs[ki] * S[i];
        }
        part[kg][vd] = yp;
        __syncthreads();
        if (tid < 64) {
            float acc = 0.f;
#pragma unroll
            for (int j = 0; j < 8; j++) acc += part[j][tid];
            y[off + tid] = acc;
        }
    }
}

// ---------------- routing: one warp per token ----------------------------
__global__ __launch_bounds__(32) void route_k(const float* __restrict__ h,
                                              const float* __restrict__ conf_w,
                                              const float* __restrict__ conf_b,
                                              const float* __restrict__ Wa,
                                              const float* __restrict__ ba,
                                              const float* __restrict__ cap,
                                              int* cnt, int* list, float* gate) {
    int n = blockIdx.x, lane = threadIdx.x;
    const float* hr = h + (size_t)n * CDIM;
    float pc[8], pa[8];
#pragma unroll
    for (int e = 0; e < 8; e++) { pc[e] = 0.f; pa[e] = 0.f; }
    for (int c = lane; c < CDIM; c += 32) {
        float hv = hr[c];
#pragma unroll
        for (int e = 0; e < 8; e++) {
            pc[e] += hv * conf_w[e * CDIM + c];
            pa[e] += hv * Wa[c * 8 + e];
        }
    }
#pragma unroll
    for (int off = 16; off; off >>= 1)
#pragma unroll
        for (int e = 0; e < 8; e++) {
            pc[e] += __shfl_xor_sync(0xffffffffu, pc[e], off);
            pa[e] += __shfl_xor_sync(0xffffffffu, pa[e], off);
        }
    if (lane == 0) {
        float aff[8], bids[8];
        float mx = -1e30f;
#pragma unroll
        for (int e = 0; e < 8; e++) { aff[e] = pa[e] + ba[e]; mx = fmaxf(mx, aff[e]); }
        float ssum = 0.f, ex[8];
#pragma unroll
        for (int e = 0; e < 8; e++) { ex[e] = expf(aff[e] - mx); ssum += ex[e]; }
#pragma unroll
        for (int e = 0; e < 8; e++) {
            float conf = 1.f / (1.f + expf(-(pc[e] + conf_b[e])));
            bids[e] = conf * cap[e] + ex[e] / ssum;
        }
        int e0 = 0;
        for (int e = 1; e < 8; e++) if (bids[e] > bids[e0]) e0 = e;
        int e1 = -1;
        for (int e = 0; e < 8; e++)
            if (e != e0 && (e1 < 0 || bids[e] > bids[e1])) e1 = e;
        float v0 = bids[e0], v1 = bids[e1];
        float w0e = expf(v0 - v0), w1e = expf(v1 - v0);
        float s = w0e + w1e;
        float w0 = w0e / s, w1 = w1e / s;
        int p0 = atomicAdd(&cnt[e0], 1); list[e0 * BTOK + p0] = n; gate[e0 * BTOK + p0] = w0;
        int p1 = atomicAdd(&cnt[e1], 1); list[e1 * BTOK + p1] = n; gate[e1 * BTOK + p1] = w1;
    }
}

__global__ void zero_cnt_k(int* cnt) { if (threadIdx.x < 8) cnt[threadIdx.x] = 0; }

__global__ __launch_bounds__(256) void outinit_k(const float* __restrict__ xatt,
                                                 const float* __restrict__ v,
                                                 float* __restrict__ out, int writeV) {
    size_t i = (size_t)blockIdx.x * 256 + threadIdx.x;
    if (i < M4) {
        out[i] = xatt[i];
        if (writeV) out[M4 + i] = v[i];
    }
}

// ---------------- tiny cross-attention over P=4 prefix slots --------------
__global__ __launch_bounds__(256) void attn_k(const float* __restrict__ qbuf,
                                              const float* __restrict__ kbuf,
                                              const float* __restrict__ vbuf,
                                              float* __restrict__ obuf,
                                              const int* cnt) {
    int m = blockIdx.x;
    if (m >= *cnt) return;
    int tid = threadIdx.x;
    __shared__ float sc[16][4], aw[16][4];

    int pair = tid >> 2, sub = tid & 3;    // 64 (head, p) pairs, 4 threads each
    int hh = pair >> 2, pp = pair & 3;
    const float* q  = qbuf + (size_t)m * CDIM + hh * HSD;
    const float* kp = kbuf + ((size_t)m * PD + pp) * CDIM + hh * HSD;
    float s = 0.f;
    for (int i = sub; i < HSD; i += 4) s += q[i] * kp[i];
    s += __shfl_xor_sync(0xffffffffu, s, 1);
    s += __shfl_xor_sync(0xffffffffu, s, 2);
    if (sub == 0) sc[hh][pp] = s * 0.125f;   // 1/sqrt(64)
    __syncthreads();
    if (tid < 16) {
        float m0 = fmaxf(fmaxf(sc[tid][0], sc[tid][1]), fmaxf(sc[tid][2], sc[tid][3]));
        float e0 = expf(sc[tid][0] - m0), e1 = expf(sc[tid][1] - m0);
        float e2 = expf(sc[tid][2] - m0), e3 = expf(sc[tid][3] - m0);
        float ssum = e0 + e1 + e2 + e3;
        aw[tid][0] = e0 / ssum; aw[tid][1] = e1 / ssum;
        aw[tid][2] = e2 / ssum; aw[tid][3] = e3 / ssum;
    }
    __syncthreads();
    for (int c = tid; c < CDIM; c += 256) {
        int h2 = c >> 6;
        float o = 0.f;
#pragma unroll
        for (int p = 0; p < 4; p++)
            o += aw[h2][p] * vbuf[((size_t)m * PD + p) * CDIM + c];
        obuf[(size_t)m * CDIM + c] = o;
    }
}

// ---------------- host side ----------------------------------------------
static void launch_gemm(const float* A, const float* A2, const float* B, float* C,
                        int M, int N, int K, int lda, int ldb, int ldc,
                        const int* cnt, int cntMul, const int* gidx, int gmode,
                        int epi, const float* bias, const float* res,
                        const float* mul, const float* gate, float* outAdd) {
    GArgs p;
    p.A = A; p.A2 = A2; p.B = B; p.C = C;
    p.M = M; p.N = N; p.K = K; p.lda = lda; p.ldb = ldb; p.ldc = ldc;
    p.cnt = cnt; p.cntMul = cntMul; p.gidx = gidx; p.gmode = gmode;
    p.epi = epi; p.bias = bias; p.res = res; p.mul = mul; p.gate = gate;
    p.outAdd = outAdd;
    dim3 grid(N / 64, M / 64);
    gemm_k<<<grid, 256>>>(p);
}

extern "C" void kernel_launch(void* const* d_in, const int* in_sizes, int n_in,
                              void* d_out, int out_size) {
    const float* x      = (const float*)d_in[0];
    const float* cap    = (const float*)d_in[2];
    const float* ln1w   = (const float*)d_in[3];
    const float* ln1b   = (const float*)d_in[4];
    const float* ln2w   = (const float*)d_in[5];
    const float* ln2b   = (const float*)d_in[6];
    const float* Wr     = (const float*)d_in[7];
    const float* Wk     = (const float*)d_in[8];
    const float* Wv     = (const float*)d_in[9];
    const float* Ww     = (const float*)d_in[10];
    const float* w_bias = (const float*)d_in[11];
    const float* Wo     = (const float*)d_in[12];
    const float* conf_w = (const float*)d_in[13];
    const float* conf_b = (const float*)d_in[14];
    const float* Wa     = (const float*)d_in[17];
    const float* ba     = (const float*)d_in[18];
    const float* Wb     = (const float*)d_in[19];
    const float* ffn_Wr = (const float*)d_in[20];
    const float* ffn_Wk = (const float*)d_in[21];
    const float* ffn_Wv = (const float*)d_in[22];
    const float* tr_Wq  = (const float*)d_in[23];
    const float* tr_Wk  = (const float*)d_in[24];
    const float* tr_Wv  = (const float*)d_in[25];
    const float* tr_Wo  = (const float*)d_in[26];
    float* out = (float*)d_out;

    float* base = nullptr;
    cudaGetSymbolAddress((void**)&base, g_scratch);

    float* xln   = base;
    float* rb    = base + 1 * M4;
    float* kb    = base + 2 * M4;
    float* vb    = base + 3 * M4;
    float* wb    = base + 4 * M4;
    float* state = base + 5 * M4;
    float* xatt  = base + 6 * M4;
    float* hbuf  = base + 7 * M4;
    float* qbuf  = base + 8 * M4;
    float* gbuf  = base + 9 * M4;
    float* obuf  = base + 10 * M4;
    float* kkbuf = base + 11 * M4;
    float* pbuf  = kkbuf + M16;
    float* kpbuf = pbuf + M16;
    float* vpbuf = kpbuf + M16;
    float* smallr = vpbuf + M16;
    int*   cnt  = (int*)smallr;
    int*   list = cnt + 8;
    float* gate = (float*)(list + 8 * BTOK);

    int writeV = (out_size >= (int)(2 * M4)) ? 1 : 0;

    // 1) LN1
    ln_k<<<BTOK, 256>>>(x, ln1w, ln1b, xln);
    // 2) r, k, v, w projections (w fused sigmoid+bias)
    launch_gemm(xln, nullptr, Wr, rb, BTOK, CDIM, CDIM, CDIM, CDIM, CDIM,
                nullptr, 1, nullptr, 0, 0, nullptr, nullptr, nullptr, nullptr, nullptr);
    launch_gemm(xln, nullptr, Wk, kb, BTOK, CDIM, CDIM, CDIM, CDIM, CDIM,
                nullptr, 1, nullptr, 0, 0, nullptr, nullptr, nullptr, nullptr, nullptr);
    launch_gemm(xln, nullptr, Wv, vb, BTOK, CDIM, CDIM, CDIM, CDIM, CDIM,
                nullptr, 1, nullptr, 0, 0, nullptr, nullptr, nullptr, nullptr, nullptr);
    launch_gemm(xln, nullptr, Ww, wb, BTOK, CDIM, CDIM, CDIM, CDIM, CDIM,
                nullptr, 1, nullptr, 0, 1, w_bias, nullptr, nullptr, nullptr, nullptr);
    // 3) RWKV scan
    scan_k<<<32, 512>>>(rb, kb, vb, wb, state);
    // 4) x_after_att = x + state @ Wo
    launch_gemm(state, nullptr, Wo, xatt, BTOK, CDIM, CDIM, CDIM, CDIM, CDIM,
                nullptr, 1, nullptr, 0, 7, nullptr, x, nullptr, nullptr, nullptr);
    // 5) LN2
    ln_k<<<BTOK, 256>>>(xatt, ln2w, ln2b, hbuf);
    // 6) routing -> per-expert lists
    zero_cnt_k<<<1, 32>>>(cnt);
    route_k<<<BTOK, 32>>>(hbuf, conf_w, conf_b, Wa, ba, cap, cnt, list, gate);
    // 7) out init: x_out = x_after_att (experts add on top); second half = v_flat
    outinit_k<<<(int)((M4 + 255) / 256), 256>>>(xatt, vb, out, writeV);

    // 8) FFN experts (0..5), sparse dispatch
    for (int e = 0; e < NREXP; e++) {
        const int* cl = list + e * BTOK;
        const float* cg = gate + e * BTOK;
        launch_gemm(hbuf, nullptr, ffn_Wk + (size_t)e * CDIM * FFDIM, kkbuf,
                    BTOK, FFDIM, CDIM, CDIM, FFDIM, FFDIM,
                    cnt + e, 1, cl, 1, 2, nullptr, nullptr, nullptr, nullptr, nullptr);
        launch_gemm(hbuf, nullptr, ffn_Wr + (size_t)e * CDIM * CDIM, gbuf,
                    BTOK, CDIM, CDIM, CDIM, CDIM, CDIM,
                    cnt + e, 1, cl, 1, 3, nullptr, nullptr, nullptr, nullptr, nullptr);
        launch_gemm(kkbuf, nullptr, ffn_Wv + (size_t)e * FFDIM * CDIM, nullptr,
                    BTOK, CDIM, FFDIM, FFDIM, CDIM, CDIM,
                    cnt + e, 1, cl, 0, 5, nullptr, nullptr, gbuf, cg, out);
    }

    // 9) transformer experts (6,7), sparse dispatch
    for (int t = 0; t < 2; t++) {
        int e = NREXP + t;
        const int* cl = list + e * BTOK;
        const float* cg = gate + e * BTOK;
        // q = gather(h) @ tr_Wq[t]
        launch_gemm(hbuf, nullptr, tr_Wq + (size_t)t * CDIM * CDIM, qbuf,
                    BTOK, CDIM, CDIM, CDIM, CDIM, CDIM,
                    cnt + e, 1, cl, 1, 0, nullptr, nullptr, nullptr, nullptr, nullptr);
        // prefix = tanh( concat(h, state) @ Wb )   (M x 4096, K = 2048)
        launch_gemm(hbuf, state, Wb, pbuf,
                    BTOK, FFDIM, 2 * CDIM, CDIM, FFDIM, FFDIM,
                    cnt + e, 1, cl, 2, 4, nullptr, nullptr, nullptr, nullptr, nullptr);
        // kp = prefix(view 4M x 1024) @ tr_Wk[t]
        launch_gemm(pbuf, nullptr, tr_Wk + (size_t)t * CDIM * CDIM, kpbuf,
                    BTOK * PD, CDIM, CDIM, CDIM, CDIM, CDIM,
                    cnt + e, PD, nullptr, 0, 0, nullptr, nullptr, nullptr, nullptr, nullptr);
        // vp = prefix @ tr_Wv[t]
        launch_gemm(pbuf, nullptr, tr_Wv + (size_t)t * CDIM * CDIM, vpbuf,
                    BTOK * PD, CDIM, CDIM, CDIM, CDIM, CDIM,
                    cnt + e, PD, nullptr, 0, 0, nullptr, nullptr, nullptr, nullptr, nullptr);
        // softmax cross-attention over P=4
        attn_k<<<BTOK, 256>>>(qbuf, kpbuf, vpbuf, obuf, cnt + e);
        // out += gate * (obuf @ tr_Wo[t])  (scatter)
        launch_gemm(obuf, nullptr, tr_Wo + (size_t)t * CDIM * CDIM, nullptr,
                    BTOK, CDIM, CDIM, CDIM, CDIM, CDIM,
                    cnt + e, 1, cl, 0, 6, nullptr, nullptr, nullptr, cg, out);
    }
}

// round 4
// speedup vs baseline: 1.1231x; 1.1231x over previous
#include <cuda_runtime.h>
#include <math.h>

// Problem constants
#define BTOK 4096          // B*T
#define CDIM 1024
#define FFDIM 4096
#define EEXP 8
#define NREXP 6
#define HN 16
#define HSD 64
#define PD 4
#define TLEN 2048

static const size_t M4  = (size_t)BTOK * CDIM;    // 4,194,304
static const size_t M16 = (size_t)BTOK * FFDIM;   // 16,777,216

// ---------------- scratch (static device allocation; no cudaMalloc) -------
__device__ float g_scratch[11ull * 4194304ull + 4ull * 16777216ull + 131072ull];

// ---------------- generic fp32 tiled GEMM (128x128x16, 8x8/thread) -------
struct GArgs {
    const float* A;
    const float* A2;     // second half for concat mode
    const float* B;
    float* C;
    int M, N, K, lda, ldb, ldc;
    const int* cnt;      // if non-null, effective M = (*cnt)*cntMul
    int cntMul;
    const int* gidx;     // gather rows for A (gmode 1/2) and scatter rows (epi 5/6)
    int gmode;           // 0 none, 1 gather, 2 concat(A|A2) gather
    int epi;             // 0 plain, 1 sigmoid(acc+bias), 2 relu^2, 3 sigmoid,
                         // 4 tanh, 5 out+=gate*mul*acc (scatter), 6 out+=gate*acc (scatter),
                         // 7 acc+res
    const float* bias;
    const float* res;
    const float* mul;
    const float* gate;
    float* outAdd;
};

__global__ __launch_bounds__(256) void gemm_k(GArgs p) {
    int effM = p.M;
    if (p.cnt) {
        int c = (*p.cnt) * p.cntMul;
        effM = c < p.M ? c : p.M;
    }
    int m0 = blockIdx.y * 128, n0 = blockIdx.x * 128;
    if (m0 >= effM) return;

    __shared__ float As[2][16][128];
    __shared__ float Bs[2][16][128];

    int tid = threadIdx.x;
    int tx = tid & 15, ty = tid >> 4;

    // A-tile load mapping: 128 rows x 16 cols, each thread 2 float4
    int aR  = tid >> 2;          // 0..63 -> rows aR, aR+64
    int aC4 = (tid & 3) << 2;    // k-offset 0,4,8,12
    // B-tile load mapping: 16 rows x 128 cols, each thread 2 float4
    int bR = tid >> 5;           // 0..7 -> rows bR, bR+8
    int bC = (tid & 31) << 2;    // 0..124

    int gm0 = m0 + aR, gm1 = m0 + aR + 64;
    int cl0 = gm0 < p.M ? gm0 : p.M - 1;
    int cl1 = gm1 < p.M ? gm1 : p.M - 1;
    int arow0, arow1;
    if (p.gmode == 0) { arow0 = cl0; arow1 = cl1; }
    else {
        arow0 = p.gidx[cl0]; arow1 = p.gidx[cl1];
        arow0 = ((unsigned)arow0 < (unsigned)BTOK) ? arow0 : 0;
        arow1 = ((unsigned)arow1 < (unsigned)BTOK) ? arow1 : 0;
    }

    float acc[8][8];
#pragma unroll
    for (int i = 0; i < 8; i++)
#pragma unroll
        for (int j = 0; j < 8; j++) acc[i][j] = 0.f;

    int nK = p.K >> 4;

    float4 va0, va1, vb0, vb1;

    // ---- tile loader (into registers) ----
    auto ldTiles = [&](int k0) {
        if (p.gmode == 2) {
            int col = k0 + aC4;
            const float* s0 = (col < CDIM)
                ? (p.A  + (size_t)arow0 * CDIM + col)
                : (p.A2 + (size_t)arow0 * CDIM + (col - CDIM));
            const float* s1 = (col < CDIM)
                ? (p.A  + (size_t)arow1 * CDIM + col)
                : (p.A2 + (size_t)arow1 * CDIM + (col - CDIM));
            va0 = *(const float4*)s0;
            va1 = *(const float4*)s1;
        } else {
            va0 = *(const float4*)(p.A + (size_t)arow0 * p.lda + k0 + aC4);
            va1 = *(const float4*)(p.A + (size_t)arow1 * p.lda + k0 + aC4);
        }
        vb0 = *(const float4*)(p.B + (size_t)(k0 + bR)     * p.ldb + n0 + bC);
        vb1 = *(const float4*)(p.B + (size_t)(k0 + bR + 8) * p.ldb + n0 + bC);
    };
    auto stTiles = [&](int buf) {
        As[buf][aC4 + 0][aR] = va0.x;
        As[buf][aC4 + 1][aR] = va0.y;
        As[buf][aC4 + 2][aR] = va0.z;
        As[buf][aC4 + 3][aR] = va0.w;
        As[buf][aC4 + 0][aR + 64] = va1.x;
        As[buf][aC4 + 1][aR + 64] = va1.y;
        As[buf][aC4 + 2][aR + 64] = va1.z;
        As[buf][aC4 + 3][aR + 64] = va1.w;
        *(float4*)&Bs[buf][bR][bC]     = vb0;
        *(float4*)&Bs[buf][bR + 8][bC] = vb1;
    };

    // prologue: tile 0 -> buf 0
    ldTiles(0);
    stTiles(0);
    __syncthreads();

    int cur = 0;
    for (int t = 0; t < nK; t++) {
        if (t + 1 < nK) ldTiles((t + 1) << 4);

#pragma unroll
        for (int k = 0; k < 16; k++) {
            float a[8], b[8];
            *(float4*)&a[0] = *(float4*)&As[cur][k][ty << 2];
            *(float4*)&a[4] = *(float4*)&As[cur][k][64 + (ty << 2)];
            *(float4*)&b[0] = *(float4*)&Bs[cur][k][tx << 2];
            *(float4*)&b[4] = *(float4*)&Bs[cur][k][64 + (tx << 2)];
#pragma unroll
            for (int i = 0; i < 8; i++)
#pragma unroll
                for (int j = 0; j < 8; j++) acc[i][j] += a[i] * b[j];
        }

        if (t + 1 < nK) {
            stTiles(cur ^ 1);
            __syncthreads();
            cur ^= 1;
        }
    }

    // ---- epilogue: 2x2 quadrants of 4x4 ----
#pragma unroll
    for (int qi = 0; qi < 2; qi++) {
#pragma unroll
        for (int i = 0; i < 4; i++) {
            int m = m0 + qi * 64 + (ty << 2) + i;
            if (m >= effM) continue;
#pragma unroll
            for (int qj = 0; qj < 2; qj++) {
#pragma unroll
                for (int j = 0; j < 4; j++) {
                    int n = n0 + qj * 64 + (tx << 2) + j;
                    float v = acc[qi * 4 + i][qj * 4 + j];
                    switch (p.epi) {
                        case 0: p.C[(size_t)m * p.ldc + n] = v; break;
                        case 1: p.C[(size_t)m * p.ldc + n] =
                                    1.f / (1.f + expf(-(v + p.bias[n]))); break;
                        case 2: { float rr = v > 0.f ? v : 0.f;
                                  p.C[(size_t)m * p.ldc + n] = rr * rr; } break;
                        case 3: p.C[(size_t)m * p.ldc + n] =
                                    1.f / (1.f + expf(-v)); break;
                        case 4: p.C[(size_t)m * p.ldc + n] = tanhf(v); break;
                        case 5: { int r = p.gidx[m];
                                  p.outAdd[(size_t)r * CDIM + n] +=
                                      p.gate[m] * p.mul[(size_t)m * CDIM + n] * v; } break;
                        case 6: { int r = p.gidx[m];
                                  p.outAdd[(size_t)r * CDIM + n] += p.gate[m] * v; } break;
                        case 7: p.C[(size_t)m * p.ldc + n] =
                                    v + p.res[(size_t)m * p.ldc + n]; break;
                    }
                }
            }
        }
    }
}

// ---------------- LayerNorm (one block per row) ---------------------------
__global__ __launch_bounds__(256) void ln_k(const float* __restrict__ x,
                                            const float* __restrict__ w,
                                            const float* __restrict__ b,
                                            float* __restrict__ y) {
    int row = blockIdx.x, tid = threadIdx.x;
    const float* xr = x + (size_t)row * CDIM;
    float v[4], s = 0.f, s2 = 0.f;
#pragma unroll
    for (int i = 0; i < 4; i++) {
        v[i] = xr[tid + 256 * i];
        s += v[i]; s2 += v[i] * v[i];
    }
#pragma unroll
    for (int off = 16; off; off >>= 1) {
        s  += __shfl_xor_sync(0xffffffffu, s, off);
        s2 += __shfl_xor_sync(0xffffffffu, s2, off);
    }
    __shared__ float rs[8], rs2[8];
    int wid = tid >> 5, lane = tid & 31;
    if (lane == 0) { rs[wid] = s; rs2[wid] = s2; }
    __syncthreads();
    if (tid == 0) {
        float S = 0.f, S2 = 0.f;
        for (int i = 0; i < 8; i++) { S += rs[i]; S2 += rs2[i]; }
        rs[0] = S; rs2[0] = S2;
    }
    __syncthreads();
    float mean = rs[0] * (1.f / 1024.f);
    float var  = rs2[0] * (1.f / 1024.f) - mean * mean;
    float inv  = rsqrtf(var + 1e-5f);
#pragma unroll
    for (int i = 0; i < 4; i++) {
        int c = tid + 256 * i;
        y[(size_t)row * CDIM + c] = (v[i] - mean) * inv * w[c] + b[c];
    }
}

// ---------------- RWKV scan: one block per (b,h), state in registers ------
__global__ __launch_bounds__(512) void scan_k(const float* __restrict__ r,
                                              const float* __restrict__ k,
                                              const float* __restrict__ v,
                                              const float* __restrict__ w,
                                              float* __restrict__ y) {
    int bh = blockIdx.x;
    int b = bh >> 4, h = bh & 15;
    int tid = threadIdx.x;
    int vd = tid & 63, kg = tid >> 6;

    __shared__ float rs[64], ks[64], vs[64], ws[64];
    __shared__ float part[8][64];

    float S[8];
#pragma unroll
    for (int i = 0; i < 8; i++) S[i] = 0.f;

    size_t base = (size_t)b * TLEN * CDIM + (size_t)h * HSD;
    for (int t = 0; t < TLEN; t++) {
        size_t off = base + (size_t)t * CDIM;
        if (tid < 256) {
            int which = tid >> 6, j = tid & 63;
            if (which == 0)      rs[j] = r[off + j];
            else if (which == 1) ks[j] = k[off + j];
            else if (which == 2) vs[j] = v[off + j];
            else                 ws[j] = w[off + j];
        }
        __syncthreads();
        float yp = 0.f, vv = vs[vd];
#pragma unroll
        for (int i = 0; i < 8; i++) {
            int ki = kg * 8 + i;
            S[i] = S[i] * ws[ki] + ks[ki] * vv;
            yp += rs[ki] * S[i];
        }
        part[kg][vd] = yp;
        __syncthreads();
        if (tid < 64) {
            float acc = 0.f;
#pragma unroll
            for (int j = 0; j < 8; j++) acc += part[j][tid];
            y[off + tid] = acc;
        }
    }
}

// ---------------- routing: one warp per token ----------------------------
__global__ __launch_bounds__(32) void route_k(const float* __restrict__ h,
                                              const float* __restrict__ conf_w,
                                              const float* __restrict__ conf_b,
                                              const float* __restrict__ Wa,
                                              const float* __restrict__ ba,
                                              const float* __restrict__ cap,
                                              int* cnt, int* list, float* gate) {
    int n = blockIdx.x, lane = threadIdx.x;
    const float* hr = h + (size_t)n * CDIM;
    float pc[8], pa[8];
#pragma unroll
    for (int e = 0; e < 8; e++) { pc[e] = 0.f; pa[e] = 0.f; }
    for (int c = lane; c < CDIM; c += 32) {
        float hv = hr[c];
#pragma unroll
        for (int e = 0; e < 8; e++) {
            pc[e] += hv * conf_w[e * CDIM + c];
            pa[e] += hv * Wa[c * 8 + e];
        }
    }
#pragma unroll
    for (int off = 16; off; off >>= 1)
#pragma unroll
        for (int e = 0; e < 8; e++) {
            pc[e] += __shfl_xor_sync(0xffffffffu, pc[e], off);
            pa[e] += __shfl_xor_sync(0xffffffffu, pa[e], off);
        }
    if (lane == 0) {
        float aff[8], bids[8];
        float mx = -1e30f;
#pragma unroll
        for (int e = 0; e < 8; e++) { aff[e] = pa[e] + ba[e]; mx = fmaxf(mx, aff[e]); }
        float ssum = 0.f, ex[8];
#pragma unroll
        for (int e = 0; e < 8; e++) { ex[e] = expf(aff[e] - mx); ssum += ex[e]; }
#pragma unroll
        for (int e = 0; e < 8; e++) {
            float conf = 1.f / (1.f + expf(-(pc[e] + conf_b[e])));
            bids[e] = conf * cap[e] + ex[e] / ssum;
        }
        int e0 = 0;
        for (int e = 1; e < 8; e++) if (bids[e] > bids[e0]) e0 = e;
        int e1 = -1;
        for (int e = 0; e < 8; e++)
            if (e != e0 && (e1 < 0 || bids[e] > bids[e1])) e1 = e;
        float v0 = bids[e0], v1 = bids[e1];
        float w0e = expf(v0 - v0), w1e = expf(v1 - v0);
        float s = w0e + w1e;
        float w0 = w0e / s, w1 = w1e / s;
        int p0 = atomicAdd(&cnt[e0], 1); list[e0 * BTOK + p0] = n; gate[e0 * BTOK + p0] = w0;
        int p1 = atomicAdd(&cnt[e1], 1); list[e1 * BTOK + p1] = n; gate[e1 * BTOK + p1] = w1;
    }
}

__global__ void zero_cnt_k(int* cnt) { if (threadIdx.x < 8) cnt[threadIdx.x] = 0; }

__global__ __launch_bounds__(256) void outinit_k(const float* __restrict__ xatt,
                                                 const float* __restrict__ v,
                                                 float* __restrict__ out, int writeV) {
    size_t i = (size_t)blockIdx.x * 256 + threadIdx.x;
    if (i < M4) {
        out[i] = xatt[i];
        if (writeV) out[M4 + i] = v[i];
    }
}

// ---------------- tiny cross-attention over P=4 prefix slots --------------
__global__ __launch_bounds__(256) void attn_k(const float* __restrict__ qbuf,
                                              const float* __restrict__ kbuf,
                                              const float* __restrict__ vbuf,
                                              float* __restrict__ obuf,
                                              const int* cnt) {
    int m = blockIdx.x;
    if (m >= *cnt) return;
    int tid = threadIdx.x;
    __shared__ float sc[16][4], aw[16][4];

    int pair = tid >> 2, sub = tid & 3;    // 64 (head, p) pairs, 4 threads each
    int hh = pair >> 2, pp = pair & 3;
    const float* q  = qbuf + (size_t)m * CDIM + hh * HSD;
    const float* kp = kbuf + ((size_t)m * PD + pp) * CDIM + hh * HSD;
    float s = 0.f;
    for (int i = sub; i < HSD; i += 4) s += q[i] * kp[i];
    s += __shfl_xor_sync(0xffffffffu, s, 1);
    s += __shfl_xor_sync(0xffffffffu, s, 2);
    if (sub == 0) sc[hh][pp] = s * 0.125f;   // 1/sqrt(64)
    __syncthreads();
    if (tid < 16) {
        float m0 = fmaxf(fmaxf(sc[tid][0], sc[tid][1]), fmaxf(sc[tid][2], sc[tid][3]));
        float e0 = expf(sc[tid][0] - m0), e1 = expf(sc[tid][1] - m0);
        float e2 = expf(sc[tid][2] - m0), e3 = expf(sc[tid][3] - m0);
        float ssum = e0 + e1 + e2 + e3;
        aw[tid][0] = e0 / ssum; aw[tid][1] = e1 / ssum;
        aw[tid][2] = e2 / ssum; aw[tid][3] = e3 / ssum;
    }
    __syncthreads();
    for (int c = tid; c < CDIM; c += 256) {
        int h2 = c >> 6;
        float o = 0.f;
#pragma unroll
        for (int p = 0; p < 4; p++)
            o += aw[h2][p] * vbuf[((size_t)m * PD + p) * CDIM + c];
        obuf[(size_t)m * CDIM + c] = o;
    }
}

// ---------------- host side ----------------------------------------------
static void launch_gemm(const float* A, const float* A2, const float* B, float* C,
                        int M, int N, int K, int lda, int ldb, int ldc,
                        const int* cnt, int cntMul, const int* gidx, int gmode,
                        int epi, const float* bias, const float* res,
                        const float* mul, const float* gate, float* outAdd) {
    GArgs p;
    p.A = A; p.A2 = A2; p.B = B; p.C = C;
    p.M = M; p.N = N; p.K = K; p.lda = lda; p.ldb = ldb; p.ldc = ldc;
    p.cnt = cnt; p.cntMul = cntMul; p.gidx = gidx; p.gmode = gmode;
    p.epi = epi; p.bias = bias; p.res = res; p.mul = mul; p.gate = gate;
    p.outAdd = outAdd;
    dim3 grid(N / 128, (M + 127) / 128);
    gemm_k<<<grid, 256>>>(p);
}

extern "C" void kernel_launch(void* const* d_in, const int* in_sizes, int n_in,
                              void* d_out, int out_size) {
    const float* x      = (const float*)d_in[0];
    const float* cap    = (const float*)d_in[2];
    const float* ln1w   = (const float*)d_in[3];
    const float* ln1b   = (const float*)d_in[4];
    const float* ln2w   = (const float*)d_in[5];
    const float* ln2b   = (const float*)d_in[6];
    const float* Wr     = (const float*)d_in[7];
    const float* Wk     = (const float*)d_in[8];
    const float* Wv     = (const float*)d_in[9];
    const float* Ww     = (const float*)d_in[10];
    const float* w_bias = (const float*)d_in[11];
    const float* Wo     = (const float*)d_in[12];
    const float* conf_w = (const float*)d_in[13];
    const float* conf_b = (const float*)d_in[14];
    const float* Wa     = (const float*)d_in[17];
    const float* ba     = (const float*)d_in[18];
    const float* Wb     = (const float*)d_in[19];
    const float* ffn_Wr = (const float*)d_in[20];
    const float* ffn_Wk = (const float*)d_in[21];
    const float* ffn_Wv = (const float*)d_in[22];
    const float* tr_Wq  = (const float*)d_in[23];
    const float* tr_Wk  = (const float*)d_in[24];
    const float* tr_Wv  = (const float*)d_in[25];
    const float* tr_Wo  = (const float*)d_in[26];
    float* out = (float*)d_out;

    float* base = nullptr;
    cudaGetSymbolAddress((void**)&base, g_scratch);

    float* xln   = base;
    float* rb    = base + 1 * M4;
    float* kb    = base + 2 * M4;
    float* vb    = base + 3 * M4;
    float* wb    = base + 4 * M4;
    float* state = base + 5 * M4;
    float* xatt  = base + 6 * M4;
    float* hbuf  = base + 7 * M4;
    float* qbuf  = base + 8 * M4;
    float* gbuf  = base + 9 * M4;
    float* obuf  = base + 10 * M4;
    float* kkbuf = base + 11 * M4;
    float* pbuf  = kkbuf + M16;
    float* kpbuf = pbuf + M16;
    float* vpbuf = kpbuf + M16;
    float* smallr = vpbuf + M16;
    int*   cnt  = (int*)smallr;
    int*   list = cnt + 8;
    float* gate = (float*)(list + 8 * BTOK);

    int writeV = (out_size >= (int)(2 * M4)) ? 1 : 0;

    // 1) LN1
    ln_k<<<BTOK, 256>>>(x, ln1w, ln1b, xln);
    // 2) r, k, v, w projections (w fused sigmoid+bias)
    launch_gemm(xln, nullptr, Wr, rb, BTOK, CDIM, CDIM, CDIM, CDIM, CDIM,
                nullptr, 1, nullptr, 0, 0, nullptr, nullptr, nullptr, nullptr, nullptr);
    launch_gemm(xln, nullptr, Wk, kb, BTOK, CDIM, CDIM, CDIM, CDIM, CDIM,
                nullptr, 1, nullptr, 0, 0, nullptr, nullptr, nullptr, nullptr, nullptr);
    launch_gemm(xln, nullptr, Wv, vb, BTOK, CDIM, CDIM, CDIM, CDIM, CDIM,
                nullptr, 1, nullptr, 0, 0, nullptr, nullptr, nullptr, nullptr, nullptr);
    launch_gemm(xln, nullptr, Ww, wb, BTOK, CDIM, CDIM, CDIM, CDIM, CDIM,
                nullptr, 1, nullptr, 0, 1, w_bias, nullptr, nullptr, nullptr, nullptr);
    // 3) RWKV scan
    scan_k<<<32, 512>>>(rb, kb, vb, wb, state);
    // 4) x_after_att = x + state @ Wo
    launch_gemm(state, nullptr, Wo, xatt, BTOK, CDIM, CDIM, CDIM, CDIM, CDIM,
                nullptr, 1, nullptr, 0, 7, nullptr, x, nullptr, nullptr, nullptr);
    // 5) LN2
    ln_k<<<BTOK, 256>>>(xatt, ln2w, ln2b, hbuf);
    // 6) routing -> per-expert lists
    zero_cnt_k<<<1, 32>>>(cnt);
    route_k<<<BTOK, 32>>>(hbuf, conf_w, conf_b, Wa, ba, cap, cnt, list, gate);
    // 7) out init: x_out = x_after_att (experts add on top); second half = v_flat
    outinit_k<<<(int)((M4 + 255) / 256), 256>>>(xatt, vb, out, writeV);

    // 8) FFN experts (0..5), sparse dispatch
    for (int e = 0; e < NREXP; e++) {
        const int* cl = list + e * BTOK;
        const float* cg = gate + e * BTOK;
        launch_gemm(hbuf, nullptr, ffn_Wk + (size_t)e * CDIM * FFDIM, kkbuf,
                    BTOK, FFDIM, CDIM, CDIM, FFDIM, FFDIM,
                    cnt + e, 1, cl, 1, 2, nullptr, nullptr, nullptr, nullptr, nullptr);
        launch_gemm(hbuf, nullptr, ffn_Wr + (size_t)e * CDIM * CDIM, gbuf,
                    BTOK, CDIM, CDIM, CDIM, CDIM, CDIM,
                    cnt + e, 1, cl, 1, 3, nullptr, nullptr, nullptr, nullptr, nullptr);
        launch_gemm(kkbuf, nullptr, ffn_Wv + (size_t)e * FFDIM * CDIM, nullptr,
                    BTOK, CDIM, FFDIM, FFDIM, CDIM, CDIM,
                    cnt + e, 1, cl, 0, 5, nullptr, nullptr, gbuf, cg, out);
    }

    // 9) transformer experts (6,7), sparse dispatch
    for (int t = 0; t < 2; t++) {
        int e = NREXP + t;
        const int* cl = list + e * BTOK;
        const float* cg = gate + e * BTOK;
        // q = gather(h) @ tr_Wq[t]
        launch_gemm(hbuf, nullptr, tr_Wq + (size_t)t * CDIM * CDIM, qbuf,
                    BTOK, CDIM, CDIM, CDIM, CDIM, CDIM,
                    cnt + e, 1, cl, 1, 0, nullptr, nullptr, nullptr, nullptr, nullptr);
        // prefix = tanh( concat(h, state) @ Wb )   (M x 4096, K = 2048)
        launch_gemm(hbuf, state, Wb, pbuf,
                    BTOK, FFDIM, 2 * CDIM, CDIM, FFDIM, FFDIM,
                    cnt + e, 1, cl, 2, 4, nullptr, nullptr, nullptr, nullptr, nullptr);
        // kp = prefix(view 4M x 1024) @ tr_Wk[t]
        launch_gemm(pbuf, nullptr, tr_Wk + (size_t)t * CDIM * CDIM, kpbuf,
                    BTOK * PD, CDIM, CDIM, CDIM, CDIM, CDIM,
                    cnt + e, PD, nullptr, 0, 0, nullptr, nullptr, nullptr, nullptr, nullptr);
        // vp = prefix @ tr_Wv[t]
        launch_gemm(pbuf, nullptr, tr_Wv + (size_t)t * CDIM * CDIM, vpbuf,
                    BTOK * PD, CDIM, CDIM, CDIM, CDIM, CDIM,
                    cnt + e, PD, nullptr, 0, 0, nullptr, nullptr, nullptr, nullptr, nullptr);
        // softmax cross-attention over P=4
        attn_k<<<BTOK, 256>>>(qbuf, kpbuf, vpbuf, obuf, cnt + e);
        // out += gate * (obuf @ tr_Wo[t])  (scatter)
        launch_gemm(obuf, nullptr, tr_Wo + (size_t)t * CDIM * CDIM, nullptr,
                    BTOK, CDIM, CDIM, CDIM, CDIM, CDIM,
                    cnt + e, 1, cl, 0, 6, nullptr, nullptr, nullptr, cg, out);
    }
}

// round 7
// speedup vs baseline: 1.8187x; 1.6194x over previous
#include <cuda_runtime.h>
#include <math.h>
#include <stdint.h>

// Problem constants
#define BTOK 4096          // B*T
#define CDIM 1024
#define FFDIM 4096
#define EEXP 8
#define NREXP 6
#define HN 16
#define HSD 64
#define PD 4
#define TLEN 2048

static const size_t M4  = (size_t)BTOK * CDIM;    // 4,194,304
static const size_t M16 = (size_t)BTOK * FFDIM;   // 16,777,216

// ---------------- scratch (static device allocation; no cudaMalloc) -------
__device__ float g_scratch[11ull * 4194304ull + 4ull * 16777216ull + 131072ull];

// ---------------- shared GEMM argument struct -----------------------------
struct GArgs {
    const float* A;
    const float* A2;     // second half for concat mode
    const float* B;
    float* C;
    int M, N, K, lda, ldb, ldc;
    const int* cnt;      // if non-null, effective M = (*cnt)*cntMul
    int cntMul;
    const int* gidx;     // gather rows for A (gmode 1/2) and scatter rows (epi 5/6)
    int gmode;           // 0 none, 1 gather, 2 concat(A|A2) gather
    int epi;             // 0 plain, 1 sigmoid(acc+bias), 2 relu^2, 3 sigmoid,
                         // 4 tanh, 5 out+=gate*mul*acc (scatter), 6 out+=gate*acc (scatter),
                         // 7 acc+res
    const float* bias;
    const float* res;
    const float* mul;
    const float* gate;
    float* outAdd;
};

__device__ __forceinline__ void apply_epi(const GArgs& p, int m, int n, float v) {
    switch (p.epi) {
        case 0: p.C[(size_t)m * p.ldc + n] = v; break;
        case 1: p.C[(size_t)m * p.ldc + n] =
                    1.f / (1.f + expf(-(v + p.bias[n]))); break;
        case 2: { float rr = v > 0.f ? v : 0.f;
                  p.C[(size_t)m * p.ldc + n] = rr * rr; } break;
        case 3: p.C[(size_t)m * p.ldc + n] = 1.f / (1.f + expf(-v)); break;
        case 4: p.C[(size_t)m * p.ldc + n] = tanhf(v); break;
        case 5: { int r = p.gidx[m];
                  p.outAdd[(size_t)r * CDIM + n] +=
                      p.gate[m] * p.mul[(size_t)m * CDIM + n] * v; } break;
        case 6: { int r = p.gidx[m];
                  p.outAdd[(size_t)r * CDIM + n] += p.gate[m] * v; } break;
        case 7: p.C[(size_t)m * p.ldc + n] =
                    v + p.res[(size_t)m * p.ldc + n]; break;
    }
}

// ================= fp32 SIMT GEMM (exact; routing-critical path) ==========
__global__ __launch_bounds__(256) void gemm_k(GArgs p) {
    int effM = p.M;
    if (p.cnt) {
        int c = (*p.cnt) * p.cntMul;
        effM = c < p.M ? c : p.M;
    }
    int m0 = blockIdx.y * 128, n0 = blockIdx.x * 128;
    if (m0 >= effM) return;

    __shared__ float As[2][16][128];
    __shared__ float Bs[2][16][128];

    int tid = threadIdx.x;
    int tx = tid & 15, ty = tid >> 4;

    int aR  = tid >> 2;
    int aC4 = (tid & 3) << 2;
    int bR = tid >> 5;
    int bC = (tid & 31) << 2;

    int gm0 = m0 + aR, gm1 = m0 + aR + 64;
    int cl0 = gm0 < p.M ? gm0 : p.M - 1;
    int cl1 = gm1 < p.M ? gm1 : p.M - 1;
    int arow0, arow1;
    if (p.gmode == 0) { arow0 = cl0; arow1 = cl1; }
    else {
        arow0 = p.gidx[cl0]; arow1 = p.gidx[cl1];
        arow0 = ((unsigned)arow0 < (unsigned)BTOK) ? arow0 : 0;
        arow1 = ((unsigned)arow1 < (unsigned)BTOK) ? arow1 : 0;
    }

    float acc[8][8];
#pragma unroll
    for (int i = 0; i < 8; i++)
#pragma unroll
        for (int j = 0; j < 8; j++) acc[i][j] = 0.f;

    int nK = p.K >> 4;
    float4 va0, va1, vb0, vb1;

    auto ldTiles = [&](int k0) {
        if (p.gmode == 2) {
            int col = k0 + aC4;
            const float* s0 = (col < CDIM)
                ? (p.A  + (size_t)arow0 * CDIM + col)
                : (p.A2 + (size_t)arow0 * CDIM + (col - CDIM));
            const float* s1 = (col < CDIM)
                ? (p.A  + (size_t)arow1 * CDIM + col)
                : (p.A2 + (size_t)arow1 * CDIM + (col - CDIM));
            va0 = *(const float4*)s0;
            va1 = *(const float4*)s1;
        } else {
            va0 = *(const float4*)(p.A + (size_t)arow0 * p.lda + k0 + aC4);
            va1 = *(const float4*)(p.A + (size_t)arow1 * p.lda + k0 + aC4);
        }
        vb0 = *(const float4*)(p.B + (size_t)(k0 + bR)     * p.ldb + n0 + bC);
        vb1 = *(const float4*)(p.B + (size_t)(k0 + bR + 8) * p.ldb + n0 + bC);
    };
    auto stTiles = [&](int buf) {
        As[buf][aC4 + 0][aR] = va0.x;
        As[buf][aC4 + 1][aR] = va0.y;
        As[buf][aC4 + 2][aR] = va0.z;
        As[buf][aC4 + 3][aR] = va0.w;
        As[buf][aC4 + 0][aR + 64] = va1.x;
        As[buf][aC4 + 1][aR + 64] = va1.y;
        As[buf][aC4 + 2][aR + 64] = va1.z;
        As[buf][aC4 + 3][aR + 64] = va1.w;
        *(float4*)&Bs[buf][bR][bC]     = vb0;
        *(float4*)&Bs[buf][bR + 8][bC] = vb1;
    };

    ldTiles(0);
    stTiles(0);
    __syncthreads();

    int cur = 0;
    for (int t = 0; t < nK; t++) {
        if (t + 1 < nK) ldTiles((t + 1) << 4);

#pragma unroll
        for (int k = 0; k < 16; k++) {
            float a[8], b[8];
            *(float4*)&a[0] = *(float4*)&As[cur][k][ty << 2];
            *(float4*)&a[4] = *(float4*)&As[cur][k][64 + (ty << 2)];
            *(float4*)&b[0] = *(float4*)&Bs[cur][k][tx << 2];
            *(float4*)&b[4] = *(float4*)&Bs[cur][k][64 + (tx << 2)];
#pragma unroll
            for (int i = 0; i < 8; i++)
#pragma unroll
                for (int j = 0; j < 8; j++) acc[i][j] += a[i] * b[j];
        }

        if (t + 1 < nK) {
            stTiles(cur ^ 1);
            __syncthreads();
            cur ^= 1;
        }
    }

#pragma unroll
    for (int qi = 0; qi < 2; qi++) {
#pragma unroll
        for (int i = 0; i < 4; i++) {
            int m = m0 + qi * 64 + (ty << 2) + i;
            if (m >= effM) continue;
#pragma unroll
            for (int qj = 0; qj < 2; qj++) {
#pragma unroll
                for (int j = 0; j < 4; j++) {
                    int n = n0 + qj * 64 + (tx << 2) + j;
                    apply_epi(p, m, n, acc[qi * 4 + i][qj * 4 + j]);
                }
            }
        }
    }
}

// ================= tf32 tensor-core GEMM (experts) ========================
__device__ __forceinline__ uint32_t f2tf32(float x) {
    uint32_t r;
    asm("cvt.rna.tf32.f32 %0, %1;" : "=r"(r) : "f"(x));
    return r;
}

__global__ __launch_bounds__(256) void gemm_tf32_k(GArgs p) {
    int effM = p.M;
    if (p.cnt) {
        int c = (*p.cnt) * p.cntMul;
        effM = c < p.M ? c : p.M;
    }
    int m0 = blockIdx.y * 128, n0 = blockIdx.x * 128;
    if (m0 >= effM) return;

    // A: m-major [128][20] pad (stride 20 -> conflict-free frag loads)
    // B: k-major [16][136] pad (stride 136 = 8 mod 32 -> conflict-free)
    __shared__ uint32_t As[2][128][20];
    __shared__ uint32_t Bs[2][16][136];

    int tid = threadIdx.x;
    int wid = tid >> 5, lane = tid & 31;
    int warpM = wid >> 2, warpN = wid & 3;      // 2 x 4 warps
    int mBase = warpM * 64, nBase = warpN * 32; // warp tile 64x32
    int lq = lane >> 2, lr = lane & 3;

    // loaders
    int aR  = tid >> 2;          // rows aR, aR+64
    int aC4 = (tid & 3) << 2;    // k offset 0,4,8,12
    int bR = tid >> 5;           // rows bR, bR+8
    int bC = (tid & 31) << 2;

    int gm0 = m0 + aR, gm1 = m0 + aR + 64;
    int cl0 = gm0 < p.M ? gm0 : p.M - 1;
    int cl1 = gm1 < p.M ? gm1 : p.M - 1;
    int arow0, arow1;
    if (p.gmode == 0) { arow0 = cl0; arow1 = cl1; }
    else {
        arow0 = p.gidx[cl0]; arow1 = p.gidx[cl1];
        arow0 = ((unsigned)arow0 < (unsigned)BTOK) ? arow0 : 0;
        arow1 = ((unsigned)arow1 < (unsigned)BTOK) ? arow1 : 0;
    }

    float acc[4][4][4];
#pragma unroll
    for (int mt = 0; mt < 4; mt++)
#pragma unroll
        for (int nt = 0; nt < 4; nt++)
#pragma unroll
            for (int r = 0; r < 4; r++) acc[mt][nt][r] = 0.f;

    int nK = p.K >> 4;
    float4 va0, va1, vb0, vb1;

    auto ldTiles = [&](int k0) {
        if (p.gmode == 2) {
            int col = k0 + aC4;
            const float* s0 = (col < CDIM)
                ? (p.A  + (size_t)arow0 * CDIM + col)
                : (p.A2 + (size_t)arow0 * CDIM + (col - CDIM));
            const float* s1 = (col < CDIM)
                ? (p.A  + (size_t)arow1 * CDIM + col)
                : (p.A2 + (size_t)arow1 * CDIM + (col - CDIM));
            va0 = *(const float4*)s0;
            va1 = *(const float4*)s1;
        } else {
            va0 = *(const float4*)(p.A + (size_t)arow0 * p.lda + k0 + aC4);
            va1 = *(const float4*)(p.A + (size_t)arow1 * p.lda + k0 + aC4);
        }
        vb0 = *(const float4*)(p.B + (size_t)(k0 + bR)     * p.ldb + n0 + bC);
        vb1 = *(const float4*)(p.B + (size_t)(k0 + bR + 8) * p.ldb + n0 + bC);
    };
    auto stTiles = [&](int buf) {
        uint4 u;
        u.x = f2tf32(va0.x); u.y = f2tf32(va0.y);
        u.z = f2tf32(va0.z); u.w = f2tf32(va0.w);
        *(uint4*)&As[buf][aR][aC4] = u;
        u.x = f2tf32(va1.x); u.y = f2tf32(va1.y);
        u.z = f2tf32(va1.z); u.w = f2tf32(va1.w);
        *(uint4*)&As[buf][aR + 64][aC4] = u;
        u.x = f2tf32(vb0.x); u.y = f2tf32(vb0.y);
        u.z = f2tf32(vb0.z); u.w = f2tf32(vb0.w);
        *(uint4*)&Bs[buf][bR][bC] = u;
        u.x = f2tf32(vb1.x); u.y = f2tf32(vb1.y);
        u.z = f2tf32(vb1.z); u.w = f2tf32(vb1.w);
        *(uint4*)&Bs[buf][bR + 8][bC] = u;
    };

    ldTiles(0);
    stTiles(0);
    __syncthreads();

    int cur = 0;
    for (int t = 0; t < nK; t++) {
        if (t + 1 < nK) ldTiles((t + 1) << 4);

#pragma unroll
        for (int ks = 0; ks < 2; ks++) {
            int k0 = ks << 3;
            uint32_t a[4][4], b[4][2];
#pragma unroll
            for (int mt = 0; mt < 4; mt++) {
                int r = mBase + mt * 16 + lq;
                a[mt][0] = As[cur][r][k0 + lr];
                a[mt][1] = As[cur][r + 8][k0 + lr];
                a[mt][2] = As[cur][r][k0 + lr + 4];
                a[mt][3] = As[cur][r + 8][k0 + lr + 4];
            }
#pragma unroll
            for (int nt = 0; nt < 4; nt++) {
                int c = nBase + nt * 8 + lq;
                b[nt][0] = Bs[cur][k0 + lr][c];
                b[nt][1] = Bs[cur][k0 + lr + 4][c];
            }
#pragma unroll
            for (int mt = 0; mt < 4; mt++)
#pragma unroll
                for (int nt = 0; nt < 4; nt++) {
                    asm volatile(
                        "mma.sync.aligned.m16n8k8.row.col.f32.tf32.tf32.f32 "
                        "{%0,%1,%2,%3},{%4,%5,%6,%7},{%8,%9},{%0,%1,%2,%3};"
                        : "+f"(acc[mt][nt][0]), "+f"(acc[mt][nt][1]),
                          "+f"(acc[mt][nt][2]), "+f"(acc[mt][nt][3])
                        : "r"(a[mt][0]), "r"(a[mt][1]), "r"(a[mt][2]), "r"(a[mt][3]),
                          "r"(b[nt][0]), "r"(b[nt][1]));
                }
        }

        if (t + 1 < nK) {
            stTiles(cur ^ 1);
            __syncthreads();
            cur ^= 1;
        }
    }

    // epilogue: mma fragment layout -> (m, n)
#pragma unroll
    for (int mt = 0; mt < 4; mt++) {
#pragma unroll
        for (int half = 0; half < 2; half++) {
            int m = m0 + mBase + mt * 16 + lq + half * 8;
            if (m >= effM) continue;
#pragma unroll
            for (int nt = 0; nt < 4; nt++) {
                int n = n0 + nBase + nt * 8 + 2 * lr;
                apply_epi(p, m, n,     acc[mt][nt][half * 2 + 0]);
                apply_epi(p, m, n + 1, acc[mt][nt][half * 2 + 1]);
            }
        }
    }
}

// ---------------- LayerNorm (one block per row) ---------------------------
__global__ __launch_bounds__(256) void ln_k(const float* __restrict__ x,
                                            const float* __restrict__ w,
                                            const float* __restrict__ b,
                                            float* __restrict__ y) {
    int row = blockIdx.x, tid = threadIdx.x;
    const float* xr = x + (size_t)row * CDIM;
    float v[4], s = 0.f, s2 = 0.f;
#pragma unroll
    for (int i = 0; i < 4; i++) {
        v[i] = xr[tid + 256 * i];
        s += v[i]; s2 += v[i] * v[i];
    }
#pragma unroll
    for (int off = 16; off; off >>= 1) {
        s  += __shfl_xor_sync(0xffffffffu, s, off);
        s2 += __shfl_xor_sync(0xffffffffu, s2, off);
    }
    __shared__ float rs[8], rs2[8];
    int wid = tid >> 5, lane = tid & 31;
    if (lane == 0) { rs[wid] = s; rs2[wid] = s2; }
    __syncthreads();
    if (tid == 0) {
        float S = 0.f, S2 = 0.f;
        for (int i = 0; i < 8; i++) { S += rs[i]; S2 += rs2[i]; }
        rs[0] = S; rs2[0] = S2;
    }
    __syncthreads();
    float mean = rs[0] * (1.f / 1024.f);
    float var  = rs2[0] * (1.f / 1024.f) - mean * mean;
    float inv  = rsqrtf(var + 1e-5f);
#pragma unroll
    for (int i = 0; i < 4; i++) {
        int c = tid + 256 * i;
        y[(size_t)row * CDIM + c] = (v[i] - mean) * inv * w[c] + b[c];
    }
}

// ---------------- RWKV scan: one block per (b,h), state in registers ------
__global__ __launch_bounds__(512) void scan_k(const float* __restrict__ r,
                                              const float* __restrict__ k,
                                              const float* __restrict__ v,
                                              const float* __restrict__ w,
                                              float* __restrict__ y) {
    int bh = blockIdx.x;
    int b = bh >> 4, h = bh & 15;
    int tid = threadIdx.x;
    int vd = tid & 63, kg = tid >> 6;

    __shared__ float rs[64], ks[64], vs[64], ws[64];
    __shared__ float part[8][64];

    float S[8];
#pragma unroll
    for (int i = 0; i < 8; i++) S[i] = 0.f;

    size_t base = (size_t)b * TLEN * CDIM + (size_t)h * HSD;
    for (int t = 0; t < TLEN; t++) {
        size_t off = base + (size_t)t * CDIM;
        if (tid < 256) {
            int which = tid >> 6, j = tid & 63;
            if (which == 0)      rs[j] = r[off + j];
            else if (which == 1) ks[j] = k[off + j];
            else if (which == 2) vs[j] = v[off + j];
            else                 ws[j] = w[off + j];
        }
        __syncthreads();
        float yp = 0.f, vv = vs[vd];
#pragma unroll
        for (int i = 0; i < 8; i++) {
            int ki = kg * 8 + i;
            S[i] = S[i] * ws[ki] + ks[ki] * vv;
            yp += rs[ki] * S[i];
        }
        part[kg][vd] = yp;
        __syncthreads();
        if (tid < 64) {
            float acc = 0.f;
#pragma unroll
            for (int j = 0; j < 8; j++) acc += part[j][tid];
            y[off + tid] = acc;
        }
    }
}

// ---------------- routing: one warp per token ----------------------------
__global__ __launch_bounds__(32) void route_k(const float* __restrict__ h,
                                              const float* __restrict__ conf_w,
                                              const float* __restrict__ conf_b,
                                              const float* __restrict__ Wa,
                                              const float* __restrict__ ba,
                                              const float* __restrict__ cap,
                                              int* cnt, int* list, float* gate) {
    int n = blockIdx.x, lane = threadIdx.x;
    const float* hr = h + (size_t)n * CDIM;
    float pc[8], pa[8];
#pragma unroll
    for (int e = 0; e < 8; e++) { pc[e] = 0.f; pa[e] = 0.f; }
    for (int c = lane; c < CDIM; c += 32) {
        float hv = hr[c];
#pragma unroll
        for (int e = 0; e < 8; e++) {
            pc[e] += hv * conf_w[e * CDIM + c];
            pa[e] += hv * Wa[c * 8 + e];
        }
    }
#pragma unroll
    for (int off = 16; off; off >>= 1)
#pragma unroll
        for (int e = 0; e < 8; e++) {
            pc[e] += __shfl_xor_sync(0xffffffffu, pc[e], off);
            pa[e] += __shfl_xor_sync(0xffffffffu, pa[e], off);
        }
    if (lane == 0) {
        float aff[8], bids[8];
        float mx = -1e30f;
#pragma unroll
        for (int e = 0; e < 8; e++) { aff[e] = pa[e] + ba[e]; mx = fmaxf(mx, aff[e]); }
        float ssum = 0.f, ex[8];
#pragma unroll
        for (int e = 0; e < 8; e++) { ex[e] = expf(aff[e] - mx); ssum += ex[e]; }
#pragma unroll
        for (int e = 0; e < 8; e++) {
            float conf = 1.f / (1.f + expf(-(pc[e] + conf_b[e])));
            bids[e] = conf * cap[e] + ex[e] / ssum;
        }
        int e0 = 0;
        for (int e = 1; e < 8; e++) if (bids[e] > bids[e0]) e0 = e;
        int e1 = -1;
        for (int e = 0; e < 8; e++)
            if (e != e0 && (e1 < 0 || bids[e] > bids[e1])) e1 = e;
        float v0 = bids[e0], v1 = bids[e1];
        float w0e = expf(v0 - v0), w1e = expf(v1 - v0);
        float s = w0e + w1e;
        float w0 = w0e / s, w1 = w1e / s;
        int p0 = atomicAdd(&cnt[e0], 1); list[e0 * BTOK + p0] = n; gate[e0 * BTOK + p0] = w0;
        int p1 = atomicAdd(&cnt[e1], 1); list[e1 * BTOK + p1] = n; gate[e1 * BTOK + p1] = w1;
    }
}

__global__ void zero_cnt_k(int* cnt) { if (threadIdx.x < 8) cnt[threadIdx.x] = 0; }

__global__ __launch_bounds__(256) void outinit_k(const float* __restrict__ xatt,
                                                 const float* __restrict__ v,
                                                 float* __restrict__ out, int writeV) {
    size_t i = (size_t)blockIdx.x * 256 + threadIdx.x;
    if (i < M4) {
        out[i] = xatt[i];
        if (writeV) out[M4 + i] = v[i];
    }
}

// ---------------- tiny cross-attention over P=4 prefix slots --------------
__global__ __launch_bounds__(256) void attn_k(const float* __restrict__ qbuf,
                                              const float* __restrict__ kbuf,
                                              const float* __restrict__ vbuf,
                                              float* __restrict__ obuf,
                                              const int* cnt) {
    int m = blockIdx.x;
    if (m >= *cnt) return;
    int tid = threadIdx.x;
    __shared__ float sc[16][4], aw[16][4];

    int pair = tid >> 2, sub = tid & 3;
    int hh = pair >> 2, pp = pair & 3;
    const float* q  = qbuf + (size_t)m * CDIM + hh * HSD;
    const float* kp = kbuf + ((size_t)m * PD + pp) * CDIM + hh * HSD;
    float s = 0.f;
    for (int i = sub; i < HSD; i += 4) s += q[i] * kp[i];
    s += __shfl_xor_sync(0xffffffffu, s, 1);
    s += __shfl_xor_sync(0xffffffffu, s, 2);
    if (sub == 0) sc[hh][pp] = s * 0.125f;
    __syncthreads();
    if (tid < 16) {
        float m0 = fmaxf(fmaxf(sc[tid][0], sc[tid][1]), fmaxf(sc[tid][2], sc[tid][3]));
        float e0 = expf(sc[tid][0] - m0), e1 = expf(sc[tid][1] - m0);
        float e2 = expf(sc[tid][2] - m0), e3 = expf(sc[tid][3] - m0);
        float ssum = e0 + e1 + e2 + e3;
        aw[tid][0] = e0 / ssum; aw[tid][1] = e1 / ssum;
        aw[tid][2] = e2 / ssum; aw[tid][3] = e3 / ssum;
    }
    __syncthreads();
    for (int c = tid; c < CDIM; c += 256) {
        int h2 = c >> 6;
        float o = 0.f;
#pragma unroll
        for (int p = 0; p < 4; p++)
            o += aw[h2][p] * vbuf[((size_t)m * PD + p) * CDIM + c];
        obuf[(size_t)m * CDIM + c] = o;
    }
}

// ---------------- host side ----------------------------------------------
static void launch_gemm_generic(bool tf32,
                        const float* A, const float* A2, const float* B, float* C,
                        int M, int N, int K, int lda, int ldb, int ldc,
                        const int* cnt, int cntMul, const int* gidx, int gmode,
                        int epi, const float* bias, const float* res,
                        const float* mul, const float* gate, float* outAdd) {
    GArgs p;
    p.A = A; p.A2 = A2; p.B = B; p.C = C;
    p.M = M; p.N = N; p.K = K; p.lda = lda; p.ldb = ldb; p.ldc = ldc;
    p.cnt = cnt; p.cntMul = cntMul; p.gidx = gidx; p.gmode = gmode;
    p.epi = epi; p.bias = bias; p.res = res; p.mul = mul; p.gate = gate;
    p.outAdd = outAdd;
    dim3 grid(N / 128, (M + 127) / 128);
    if (tf32) gemm_tf32_k<<<grid, 256>>>(p);
    else      gemm_k<<<grid, 256>>>(p);
}

#define launch_gemm(...)   launch_gemm_generic(false, __VA_ARGS__)
#define launch_gemmt(...)  launch_gemm_generic(true,  __VA_ARGS__)

extern "C" void kernel_launch(void* const* d_in, const int* in_sizes, int n_in,
                              void* d_out, int out_size) {
    const float* x      = (const float*)d_in[0];
    const float* cap    = (const float*)d_in[2];
    const float* ln1w   = (const float*)d_in[3];
    const float* ln1b   = (const float*)d_in[4];
    const float* ln2w   = (const float*)d_in[5];
    const float* ln2b   = (const float*)d_in[6];
    const float* Wr     = (const float*)d_in[7];
    const float* Wk     = (const float*)d_in[8];
    const float* Wv     = (const float*)d_in[9];
    const float* Ww     = (const float*)d_in[10];
    const float* w_bias = (const float*)d_in[11];
    const float* Wo     = (const float*)d_in[12];
    const float* conf_w = (const float*)d_in[13];
    const float* conf_b = (const float*)d_in[14];
    const float* Wa     = (const float*)d_in[17];
    const float* ba     = (const float*)d_in[18];
    const float* Wb     = (const float*)d_in[19];
    const float* ffn_Wr = (const float*)d_in[20];
    const float* ffn_Wk = (const float*)d_in[21];
    const float* ffn_Wv = (const float*)d_in[22];
    const float* tr_Wq  = (const float*)d_in[23];
    const float* tr_Wk  = (const float*)d_in[24];
    const float* tr_Wv  = (const float*)d_in[25];
    const float* tr_Wo  = (const float*)d_in[26];
    float* out = (float*)d_out;

    float* base = nullptr;
    cudaGetSymbolAddress((void**)&base, g_scratch);

    float* xln   = base;
    float* rb    = base + 1 * M4;
    float* kb    = base + 2 * M4;
    float* vb    = base + 3 * M4;
    float* wb    = base + 4 * M4;
    float* state = base + 5 * M4;
    float* xatt  = base + 6 * M4;
    float* hbuf  = base + 7 * M4;
    float* qbuf  = base + 8 * M4;
    float* gbuf  = base + 9 * M4;
    float* obuf  = base + 10 * M4;
    float* kkbuf = base + 11 * M4;
    float* pbuf  = kkbuf + M16;
    float* kpbuf = pbuf + M16;
    float* vpbuf = kpbuf + M16;
    float* smallr = vpbuf + M16;
    int*   cnt  = (int*)smallr;
    int*   list = cnt + 8;
    float* gate = (float*)(list + 8 * BTOK);

    int writeV = (out_size >= (int)(2 * M4)) ? 1 : 0;

    // ---- fp32-exact routing-critical path ----
    ln_k<<<BTOK, 256>>>(x, ln1w, ln1b, xln);
    launch_gemm(xln, nullptr, Wr, rb, BTOK, CDIM, CDIM, CDIM, CDIM, CDIM,
                nullptr, 1, nullptr, 0, 0, nullptr, nullptr, nullptr, nullptr, nullptr);
    launch_gemm(xln, nullptr, Wk, kb, BTOK, CDIM, CDIM, CDIM, CDIM, CDIM,
                nullptr, 1, nullptr, 0, 0, nullptr, nullptr, nullptr, nullptr, nullptr);
    launch_gemm(xln, nullptr, Wv, vb, BTOK, CDIM, CDIM, CDIM, CDIM, CDIM,
                nullptr, 1, nullptr, 0, 0, nullptr, nullptr, nullptr, nullptr, nullptr);
    launch_gemm(xln, nullptr, Ww, wb, BTOK, CDIM, CDIM, CDIM, CDIM, CDIM,
                nullptr, 1, nullptr, 0, 1, w_bias, nullptr, nullptr, nullptr, nullptr);
    scan_k<<<32, 512>>>(rb, kb, vb, wb, state);
    launch_gemm(state, nullptr, Wo, xatt, BTOK, CDIM, CDIM, CDIM, CDIM, CDIM,
                nullptr, 1, nullptr, 0, 7, nullptr, x, nullptr, nullptr, nullptr);
    ln_k<<<BTOK, 256>>>(xatt, ln2w, ln2b, hbuf);
    zero_cnt_k<<<1, 32>>>(cnt);
    route_k<<<BTOK, 32>>>(hbuf, conf_w, conf_b, Wa, ba, cap, cnt, list, gate);
    outinit_k<<<(int)((M4 + 255) / 256), 256>>>(xatt, vb, out, writeV);

    // ---- tf32 tensor-core expert path ----
    for (int e = 0; e < NREXP; e++) {
        const int* cl = list + e * BTOK;
        const float* cg = gate + e * BTOK;
        launch_gemmt(hbuf, nullptr, ffn_Wk + (size_t)e * CDIM * FFDIM, kkbuf,
                    BTOK, FFDIM, CDIM, CDIM, FFDIM, FFDIM,
                    cnt + e, 1, cl, 1, 2, nullptr, nullptr, nullptr, nullptr, nullptr);
        launch_gemmt(hbuf, nullptr, ffn_Wr + (size_t)e * CDIM * CDIM, gbuf,
                    BTOK, CDIM, CDIM, CDIM, CDIM, CDIM,
                    cnt + e, 1, cl, 1, 3, nullptr, nullptr, nullptr, nullptr, nullptr);
        launch_gemmt(kkbuf, nullptr, ffn_Wv + (size_t)e * FFDIM * CDIM, nullptr,
                    BTOK, CDIM, FFDIM, FFDIM, CDIM, CDIM,
                    cnt + e, 1, cl, 0, 5, nullptr, nullptr, gbuf, cg, out);
    }

    for (int t = 0; t < 2; t++) {
        int e = NREXP + t;
        const int* cl = list + e * BTOK;
        const float* cg = gate + e * BTOK;
        launch_gemmt(hbuf, nullptr, tr_Wq + (size_t)t * CDIM * CDIM, qbuf,
                    BTOK, CDIM, CDIM, CDIM, CDIM, CDIM,
                    cnt + e, 1, cl, 1, 0, nullptr, nullptr, nullptr, nullptr, nullptr);
        launch_gemmt(hbuf, state, Wb, pbuf,
                    BTOK, FFDIM, 2 * CDIM, CDIM, FFDIM, FFDIM,
                    cnt + e, 1, cl, 2, 4, nullptr, nullptr, nullptr, nullptr, nullptr);
        launch_gemmt(pbuf, nullptr, tr_Wk + (size_t)t * CDIM * CDIM, kpbuf,
                    BTOK * PD, CDIM, CDIM, CDIM, CDIM, CDIM,
                    cnt + e, PD, nullptr, 0, 0, nullptr, nullptr, nullptr, nullptr, nullptr);
        launch_gemmt(pbuf, nullptr, tr_Wv + (size_t)t * CDIM * CDIM, vpbuf,
                    BTOK * PD, CDIM, CDIM, CDIM, CDIM, CDIM,
                    cnt + e, PD, nullptr, 0, 0, nullptr, nullptr, nullptr, nullptr, nullptr);
        attn_k<<<BTOK, 256>>>(qbuf, kpbuf, vpbuf, obuf, cnt + e);
        launch_gemmt(obuf, nullptr, tr_Wo + (size_t)t * CDIM * CDIM, nullptr,
                    BTOK, CDIM, CDIM, CDIM, CDIM, CDIM,
                    cnt + e, 1, cl, 0, 6, nullptr, nullptr, nullptr, cg, out);
    }
}

// round 8
// speedup vs baseline: 2.6108x; 1.4355x over previous
#include <cuda_runtime.h>
#include <math.h>
#include <stdint.h>

// Problem constants
#define BTOK 4096          // B*T
#define CDIM 1024
#define FFDIM 4096
#define EEXP 8
#define NREXP 6
#define HN 16
#define HSD 64
#define PD 4
#define TLEN 2048

#define M4E  4194304ull
#define M16E 16777216ull

static const size_t M4  = (size_t)M4E;
static const size_t M16 = (size_t)M16E;

// ---------------- scratch (static device allocation; no cudaMalloc) -------
// layout (floats):
//   0..7  : xln, r, k, v, w, state, xatt, h           (8 * M4)
//   qb2   : 2*M4   gb6 : 6*M4   ob2 : 2*M4
//   kkb   : 6*M16  pb2 : 2*M16  kpb2: 2*M16  vpb2: 2*M16
//   small : cnt(8) list(8*4096) gate(8*4096)
__device__ float g_scratch[276955136ull];

// ---------------- shared GEMM argument struct -----------------------------
struct GArgs {
    const float* A;
    const float* A2;     // second half for concat mode
    const float* B;
    float* C;
    int M, N, K, lda, ldb, ldc;
    const int* cnt;      // fp32 kernel: *cnt ; batched kernel: cnt[z]
    int cntMul;
    const int* gidx;
    int gmode;           // 0 none, 1 gather, 2 concat(A|A2) gather
    int epi;             // 0 plain, 1 sigmoid(+bias), 2 relu^2, 3 sigmoid,
                         // 4 tanh, 5 out+=gate*mul*acc (atomic scatter),
                         // 6 out+=gate*acc (atomic scatter), 7 acc+res
    const float* bias;
    const float* res;
    const float* mul;
    const float* gate;
    float* outAdd;
    size_t sA, sB, sC, sMul, sList;   // per-z strides (batched kernel)
};

// ================= fp32 SIMT GEMM (exact; routing-critical path) ==========
__global__ __launch_bounds__(256) void gemm_k(GArgs p) {
    int effM = p.M;
    if (p.cnt) {
        int c = (*p.cnt) * p.cntMul;
        effM = c < p.M ? c : p.M;
    }
    int m0 = blockIdx.y * 128, n0 = blockIdx.x * 128;
    if (m0 >= effM) return;

    __shared__ float As[2][16][128];
    __shared__ float Bs[2][16][128];

    int tid = threadIdx.x;
    int tx = tid & 15, ty = tid >> 4;

    int aR  = tid >> 2;
    int aC4 = (tid & 3) << 2;
    int bR = tid >> 5;
    int bC = (tid & 31) << 2;

    int gm0 = m0 + aR, gm1 = m0 + aR + 64;
    int cl0 = gm0 < p.M ? gm0 : p.M - 1;
    int cl1 = gm1 < p.M ? gm1 : p.M - 1;
    int arow0, arow1;
    if (p.gmode == 0) { arow0 = cl0; arow1 = cl1; }
    else {
        arow0 = p.gidx[cl0]; arow1 = p.gidx[cl1];
        arow0 = ((unsigned)arow0 < (unsigned)BTOK) ? arow0 : 0;
        arow1 = ((unsigned)arow1 < (unsigned)BTOK) ? arow1 : 0;
    }

    float acc[8][8];
#pragma unroll
    for (int i = 0; i < 8; i++)
#pragma unroll
        for (int j = 0; j < 8; j++) acc[i][j] = 0.f;

    int nK = p.K >> 4;
    float4 va0, va1, vb0, vb1;

    auto ldTiles = [&](int k0) {
        if (p.gmode == 2) {
            int col = k0 + aC4;
            const float* s0 = (col < CDIM)
                ? (p.A  + (size_t)arow0 * CDIM + col)
                : (p.A2 + (size_t)arow0 * CDIM + (col - CDIM));
            const float* s1 = (col < CDIM)
                ? (p.A  + (size_t)arow1 * CDIM + col)
                : (p.A2 + (size_t)arow1 * CDIM + (col - CDIM));
            va0 = *(const float4*)s0;
            va1 = *(const float4*)s1;
        } else {
            va0 = *(const float4*)(p.A + (size_t)arow0 * p.lda + k0 + aC4);
            va1 = *(const float4*)(p.A + (size_t)arow1 * p.lda + k0 + aC4);
        }
        vb0 = *(const float4*)(p.B + (size_t)(k0 + bR)     * p.ldb + n0 + bC);
        vb1 = *(const float4*)(p.B + (size_t)(k0 + bR + 8) * p.ldb + n0 + bC);
    };
    auto stTiles = [&](int buf) {
        As[buf][aC4 + 0][aR] = va0.x;
        As[buf][aC4 + 1][aR] = va0.y;
        As[buf][aC4 + 2][aR] = va0.z;
        As[buf][aC4 + 3][aR] = va0.w;
        As[buf][aC4 + 0][aR + 64] = va1.x;
        As[buf][aC4 + 1][aR + 64] = va1.y;
        As[buf][aC4 + 2][aR + 64] = va1.z;
        As[buf][aC4 + 3][aR + 64] = va1.w;
        *(float4*)&Bs[buf][bR][bC]     = vb0;
        *(float4*)&Bs[buf][bR + 8][bC] = vb1;
    };

    ldTiles(0);
    stTiles(0);
    __syncthreads();

    int cur = 0;
    for (int t = 0; t < nK; t++) {
        if (t + 1 < nK) ldTiles((t + 1) << 4);

#pragma unroll
        for (int k = 0; k < 16; k++) {
            float a[8], b[8];
            *(float4*)&a[0] = *(float4*)&As[cur][k][ty << 2];
            *(float4*)&a[4] = *(float4*)&As[cur][k][64 + (ty << 2)];
            *(float4*)&b[0] = *(float4*)&Bs[cur][k][tx << 2];
            *(float4*)&b[4] = *(float4*)&Bs[cur][k][64 + (tx << 2)];
#pragma unroll
            for (int i = 0; i < 8; i++)
#pragma unroll
                for (int j = 0; j < 8; j++) acc[i][j] += a[i] * b[j];
        }

        if (t + 1 < nK) {
            stTiles(cur ^ 1);
            __syncthreads();
            cur ^= 1;
        }
    }

#pragma unroll
    for (int qi = 0; qi < 2; qi++) {
#pragma unroll
        for (int i = 0; i < 4; i++) {
            int m = m0 + qi * 64 + (ty << 2) + i;
            if (m >= effM) continue;
#pragma unroll
            for (int j = 0; j < 4; j++) {
#pragma unroll
                for (int qj = 0; qj < 2; qj++) {
                    int n = n0 + qj * 64 + (tx << 2) + j;
                    float v = acc[qi * 4 + i][qj * 4 + j];
                    switch (p.epi) {
                        case 0: p.C[(size_t)m * p.ldc + n] = v; break;
                        case 1: p.C[(size_t)m * p.ldc + n] =
                                    1.f / (1.f + expf(-(v + p.bias[n]))); break;
                        case 7: p.C[(size_t)m * p.ldc + n] =
                                    v + p.res[(size_t)m * p.ldc + n]; break;
                        default: p.C[(size_t)m * p.ldc + n] = v; break;
                    }
                }
            }
        }
    }
}

// ================= batched tf32 tensor-core GEMM (experts) ================
#define CP_A16(dst, src) \
    asm volatile("cp.async.cg.shared.global [%0], [%1], 16;" :: "r"(dst), "l"(src) : "memory")
#define CP_COMMIT() asm volatile("cp.async.commit_group;" ::: "memory")
#define CP_WAIT2()  asm volatile("cp.async.wait_group 2;" ::: "memory")

__global__ __launch_bounds__(256) void gemm_tf32_k(GArgs p) {
    int z = blockIdx.z;
    const float* Ab   = p.A + (size_t)z * p.sA;
    const float* Bb   = p.B + (size_t)z * p.sB;
    float*       Cb   = p.C + (size_t)z * p.sC;
    const int*   gidx = p.gidx ? p.gidx + (size_t)z * p.sList : nullptr;
    const float* gteb = p.gate ? p.gate + (size_t)z * p.sList : nullptr;
    const float* mulb = p.mul  ? p.mul  + (size_t)z * p.sMul  : nullptr;

    int effM = p.M;
    if (p.cnt) {
        int c = p.cnt[z] * p.cntMul;
        effM = c < p.M ? c : p.M;
    }
    int m0 = blockIdx.y * 128, n0 = blockIdx.x * 128;
    if (m0 >= effM) return;

    // 4-stage dynamic smem: A m-major [128][20] pad, B k-major [16][136] pad
    extern __shared__ float dynsmem[];
    float (*As)[128][20] = (float(*)[128][20])dynsmem;
    float (*Bs)[16][136] = (float(*)[16][136])(dynsmem + 4 * 128 * 20);

    int tid = threadIdx.x;
    int wid = tid >> 5, lane = tid & 31;
    int warpM = wid >> 2, warpN = wid & 3;      // 2 x 4 warps
    int mBase = warpM * 64, nBase = warpN * 32; // warp tile 64x32
    int lq = lane >> 2, lr = lane & 3;

    int aR  = tid >> 2;          // rows aR, aR+64
    int aC4 = (tid & 3) << 2;    // k offset 0,4,8,12
    int bR = tid >> 5;           // rows bR, bR+8
    int bC = (tid & 31) << 2;

    int gm0 = m0 + aR, gm1 = m0 + aR + 64;
    int cl0 = gm0 < p.M ? gm0 : p.M - 1;
    int cl1 = gm1 < p.M ? gm1 : p.M - 1;
    int arow0, arow1;
    if (p.gmode == 0) { arow0 = cl0; arow1 = cl1; }
    else {
        arow0 = gidx[cl0]; arow1 = gidx[cl1];
        arow0 = ((unsigned)arow0 < (unsigned)BTOK) ? arow0 : 0;
        arow1 = ((unsigned)arow1 < (unsigned)BTOK) ? arow1 : 0;
    }

    uint32_t aD0 = (uint32_t)__cvta_generic_to_shared(&As[0][aR][aC4]);
    uint32_t aD1 = (uint32_t)__cvta_generic_to_shared(&As[0][aR + 64][aC4]);
    uint32_t bD0 = (uint32_t)__cvta_generic_to_shared(&Bs[0][bR][bC]);
    uint32_t bD1 = (uint32_t)__cvta_generic_to_shared(&Bs[0][bR + 8][bC]);
    const uint32_t aStr = 128 * 20 * 4;
    const uint32_t bStr = 16 * 136 * 4;

    auto issueTile = [&](int t, int buf) {
        int k0 = t << 4;
        const float *s0, *s1;
        if (p.gmode == 2) {
            int col = k0 + aC4;
            s0 = (col < CDIM) ? (Ab + (size_t)arow0 * CDIM + col)
                              : (p.A2 + (size_t)arow0 * CDIM + (col - CDIM));
            s1 = (col < CDIM) ? (Ab + (size_t)arow1 * CDIM + col)
                              : (p.A2 + (size_t)arow1 * CDIM + (col - CDIM));
        } else {
            s0 = Ab + (size_t)arow0 * p.lda + k0 + aC4;
            s1 = Ab + (size_t)arow1 * p.lda + k0 + aC4;
        }
        CP_A16(aD0 + buf * aStr, s0);
        CP_A16(aD1 + buf * aStr, s1);
        CP_A16(bD0 + buf * bStr, Bb + (size_t)(k0 + bR)     * p.ldb + n0 + bC);
        CP_A16(bD1 + buf * bStr, Bb + (size_t)(k0 + bR + 8) * p.ldb + n0 + bC);
        CP_COMMIT();
    };

    float acc[4][4][4];
#pragma unroll
    for (int mt = 0; mt < 4; mt++)
#pragma unroll
        for (int nt = 0; nt < 4; nt++)
#pragma unroll
            for (int r = 0; r < 4; r++) acc[mt][nt][r] = 0.f;

    int nK = p.K >> 4;
    issueTile(0, 0);
    if (nK > 1) issueTile(1, 1); else CP_COMMIT();
    if (nK > 2) issueTile(2, 2); else CP_COMMIT();

    for (int t = 0; t < nK; t++) {
        CP_WAIT2();
        __syncthreads();
        if (t + 3 < nK) issueTile(t + 3, (t + 3) & 3); else CP_COMMIT();

        int cb = t & 3;
#pragma unroll
        for (int ks = 0; ks < 2; ks++) {
            int k0 = ks << 3;
            uint32_t a[4][4], b[4][2];
#pragma unroll
            for (int mt = 0; mt < 4; mt++) {
                int r = mBase + mt * 16 + lq;
                a[mt][0] = __float_as_uint(As[cb][r][k0 + lr]);
                a[mt][1] = __float_as_uint(As[cb][r + 8][k0 + lr]);
                a[mt][2] = __float_as_uint(As[cb][r][k0 + lr + 4]);
                a[mt][3] = __float_as_uint(As[cb][r + 8][k0 + lr + 4]);
            }
#pragma unroll
            for (int nt = 0; nt < 4; nt++) {
                int c = nBase + nt * 8 + lq;
                b[nt][0] = __float_as_uint(Bs[cb][k0 + lr][c]);
                b[nt][1] = __float_as_uint(Bs[cb][k0 + lr + 4][c]);
            }
#pragma unroll
            for (int mt = 0; mt < 4; mt++)
#pragma unroll
                for (int nt = 0; nt < 4; nt++) {
                    asm volatile(
                        "mma.sync.aligned.m16n8k8.row.col.f32.tf32.tf32.f32 "
                        "{%0,%1,%2,%3},{%4,%5,%6,%7},{%8,%9},{%0,%1,%2,%3};"
                        : "+f"(acc[mt][nt][0]), "+f"(acc[mt][nt][1]),
                          "+f"(acc[mt][nt][2]), "+f"(acc[mt][nt][3])
                        : "r"(a[mt][0]), "r"(a[mt][1]), "r"(a[mt][2]), "r"(a[mt][3]),
                          "r"(b[nt][0]), "r"(b[nt][1]));
                }
        }
    }

    // epilogue
#pragma unroll
    for (int mt = 0; mt < 4; mt++) {
#pragma unroll
        for (int half = 0; half < 2; half++) {
            int m = m0 + mBase + mt * 16 + lq + half * 8;
            if (m >= effM) continue;
#pragma unroll
            for (int nt = 0; nt < 4; nt++) {
                int n = n0 + nBase + nt * 8 + 2 * lr;
                float v0 = acc[mt][nt][half * 2 + 0];
                float v1 = acc[mt][nt][half * 2 + 1];
                switch (p.epi) {
                    case 0:
                        Cb[(size_t)m * p.ldc + n]     = v0;
                        Cb[(size_t)m * p.ldc + n + 1] = v1;
                        break;
                    case 2: {
                        float r0 = v0 > 0.f ? v0 : 0.f;
                        float r1 = v1 > 0.f ? v1 : 0.f;
                        Cb[(size_t)m * p.ldc + n]     = r0 * r0;
                        Cb[(size_t)m * p.ldc + n + 1] = r1 * r1;
                    } break;
                    case 3:
                        Cb[(size_t)m * p.ldc + n]     = 1.f / (1.f + expf(-v0));
                        Cb[(size_t)m * p.ldc + n + 1] = 1.f / (1.f + expf(-v1));
                        break;
                    case 4:
                        Cb[(size_t)m * p.ldc + n]     = tanhf(v0);
                        Cb[(size_t)m * p.ldc + n + 1] = tanhf(v1);
                        break;
                    case 5: {
                        int r = gidx[m]; float g = gteb[m];
                        atomicAdd(&p.outAdd[(size_t)r * CDIM + n],
                                  g * mulb[(size_t)m * CDIM + n] * v0);
                        atomicAdd(&p.outAdd[(size_t)r * CDIM + n + 1],
                                  g * mulb[(size_t)m * CDIM + n + 1] * v1);
                    } break;
                    case 6: {
                        int r = gidx[m]; float g = gteb[m];
                        atomicAdd(&p.outAdd[(size_t)r * CDIM + n],     g * v0);
                        atomicAdd(&p.outAdd[(size_t)r * CDIM + n + 1], g * v1);
                    } break;
                }
            }
        }
    }
}

// ---------------- LayerNorm (one block per row) ---------------------------
__global__ __launch_bounds__(256) void ln_k(const float* __restrict__ x,
                                            const float* __restrict__ w,
                                            const float* __restrict__ b,
                                            float* __restrict__ y) {
    int row = blockIdx.x, tid = threadIdx.x;
    const float* xr = x + (size_t)row * CDIM;
    float v[4], s = 0.f, s2 = 0.f;
#pragma unroll
    for (int i = 0; i < 4; i++) {
        v[i] = xr[tid + 256 * i];
        s += v[i]; s2 += v[i] * v[i];
    }
#pragma unroll
    for (int off = 16; off; off >>= 1) {
        s  += __shfl_xor_sync(0xffffffffu, s, off);
        s2 += __shfl_xor_sync(0xffffffffu, s2, off);
    }
    __shared__ float rs[8], rs2[8];
    int wid = tid >> 5, lane = tid & 31;
    if (lane == 0) { rs[wid] = s; rs2[wid] = s2; }
    __syncthreads();
    if (tid == 0) {
        float S = 0.f, S2 = 0.f;
        for (int i = 0; i < 8; i++) { S += rs[i]; S2 += rs2[i]; }
        rs[0] = S; rs2[0] = S2;
    }
    __syncthreads();
    float mean = rs[0] * (1.f / 1024.f);
    float var  = rs2[0] * (1.f / 1024.f) - mean * mean;
    float inv  = rsqrtf(var + 1e-5f);
#pragma unroll
    for (int i = 0; i < 4; i++) {
        int c = tid + 256 * i;
        y[(size_t)row * CDIM + c] = (v[i] - mean) * inv * w[c] + b[c];
    }
}

// ---------------- RWKV scan: one block per (b,h), state in registers ------
__global__ __launch_bounds__(512) void scan_k(const float* __restrict__ r,
                                              const float* __restrict__ k,
                                              const float* __restrict__ v,
                                              const float* __restrict__ w,
                                              float* __restrict__ y) {
    int bh = blockIdx.x;
    int b = bh >> 4, h = bh & 15;
    int tid = threadIdx.x;
    int vd = tid & 63, kg = tid >> 6;

    __shared__ float rs[64], ks[64], vs[64], ws[64];
    __shared__ float part[8][64];

    float S[8];
#pragma unroll
    for (int i = 0; i < 8; i++) S[i] = 0.f;

    size_t base = (size_t)b * TLEN * CDIM + (size_t)h * HSD;
    for (int t = 0; t < TLEN; t++) {
        size_t off = base + (size_t)t * CDIM;
        if (tid < 256) {
            int which = tid >> 6, j = tid & 63;
            if (which == 0)      rs[j] = r[off + j];
            else if (which == 1) ks[j] = k[off + j];
            else if (which == 2) vs[j] = v[off + j];
            else                 ws[j] = w[off + j];
        }
        __syncthreads();
        float yp = 0.f, vv = vs[vd];
#pragma unroll
        for (int i = 0; i < 8; i++) {
            int ki = kg * 8 + i;
            S[i] = S[i] * ws[ki] + ks[ki] * vv;
            yp += rs[ki] * S[i];
        }
        part[kg][vd] = yp;
        __syncthreads();
        if (tid < 64) {
            float acc = 0.f;
#pragma unroll
            for (int j = 0; j < 8; j++) acc += part[j][tid];
            y[off + tid] = acc;
        }
    }
}

// ---------------- routing: one warp per token ----------------------------
__global__ __launch_bounds__(32) void route_k(const float* __restrict__ h,
                                              const float* __restrict__ conf_w,
                                              const float* __restrict__ conf_b,
                                              const float* __restrict__ Wa,
                                              const float* __restrict__ ba,
                                              const float* __restrict__ cap,
                                              int* cnt, int* list, float* gate) {
    int n = blockIdx.x, lane = threadIdx.x;
    const float* hr = h + (size_t)n * CDIM;
    float pc[8], pa[8];
#pragma unroll
    for (int e = 0; e < 8; e++) { pc[e] = 0.f; pa[e] = 0.f; }
    for (int c = lane; c < CDIM; c += 32) {
        float hv = hr[c];
#pragma unroll
        for (int e = 0; e < 8; e++) {
            pc[e] += hv * conf_w[e * CDIM + c];
            pa[e] += hv * Wa[c * 8 + e];
        }
    }
#pragma unroll
    for (int off = 16; off; off >>= 1)
#pragma unroll
        for (int e = 0; e < 8; e++) {
            pc[e] += __shfl_xor_sync(0xffffffffu, pc[e], off);
            pa[e] += __shfl_xor_sync(0xffffffffu, pa[e], off);
        }
    if (lane == 0) {
        float aff[8], bids[8];
        float mx = -1e30f;
#pragma unroll
        for (int e = 0; e < 8; e++) { aff[e] = pa[e] + ba[e]; mx = fmaxf(mx, aff[e]); }
        float ssum = 0.f, ex[8];
#pragma unroll
        for (int e = 0; e < 8; e++) { ex[e] = expf(aff[e] - mx); ssum += ex[e]; }
#pragma unroll
        for (int e = 0; e < 8; e++) {
            float conf = 1.f / (1.f + expf(-(pc[e] + conf_b[e])));
            bids[e] = conf * cap[e] + ex[e] / ssum;
        }
        int e0 = 0;
        for (int e = 1; e < 8; e++) if (bids[e] > bids[e0]) e0 = e;
        int e1 = -1;
        for (int e = 0; e < 8; e++)
            if (e != e0 && (e1 < 0 || bids[e] > bids[e1])) e1 = e;
        float v0 = bids[e0], v1 = bids[e1];
        float w0e = expf(v0 - v0), w1e = expf(v1 - v0);
        float s = w0e + w1e;
        float w0 = w0e / s, w1 = w1e / s;
        int p0 = atomicAdd(&cnt[e0], 1); list[e0 * BTOK + p0] = n; gate[e0 * BTOK + p0] = w0;
        int p1 = atomicAdd(&cnt[e1], 1); list[e1 * BTOK + p1] = n; gate[e1 * BTOK + p1] = w1;
    }
}

__global__ void zero_cnt_k(int* cnt) { if (threadIdx.x < 8) cnt[threadIdx.x] = 0; }

__global__ __launch_bounds__(256) void outinit_k(const float* __restrict__ xatt,
                                                 const float* __restrict__ v,
                                                 float* __restrict__ out, int writeV) {
    size_t i = (size_t)blockIdx.x * 256 + threadIdx.x;
    if (i < M4E) {
        out[i] = xatt[i];
        if (writeV) out[M4E + i] = v[i];
    }
}

// -------- batched tiny cross-attention over P=4 prefix slots (z = expert) --
__global__ __launch_bounds__(256) void attn_k(const float* __restrict__ qb,
                                              const float* __restrict__ kb,
                                              const float* __restrict__ vb,
                                              float* __restrict__ ob,
                                              const int* __restrict__ cnt) {
    int z = blockIdx.y;
    int m = blockIdx.x;
    if (m >= cnt[z]) return;
    const float* qbuf = qb + (size_t)z * M4E;
    const float* kbuf = kb + (size_t)z * M16E;
    const float* vbuf = vb + (size_t)z * M16E;
    float* obuf = ob + (size_t)z * M4E;

    int tid = threadIdx.x;
    __shared__ float sc[16][4], aw[16][4];

    int pair = tid >> 2, sub = tid & 3;
    int hh = pair >> 2, pp = pair & 3;
    const float* q  = qbuf + (size_t)m * CDIM + hh * HSD;
    const float* kp = kbuf + ((size_t)m * PD + pp) * CDIM + hh * HSD;
    float s = 0.f;
    for (int i = sub; i < HSD; i += 4) s += q[i] * kp[i];
    s += __shfl_xor_sync(0xffffffffu, s, 1);
    s += __shfl_xor_sync(0xffffffffu, s, 2);
    if (sub == 0) sc[hh][pp] = s * 0.125f;
    __syncthreads();
    if (tid < 16) {
        float m0 = fmaxf(fmaxf(sc[tid][0], sc[tid][1]), fmaxf(sc[tid][2], sc[tid][3]));
        float e0 = expf(sc[tid][0] - m0), e1 = expf(sc[tid][1] - m0);
        float e2 = expf(sc[tid][2] - m0), e3 = expf(sc[tid][3] - m0);
        float ssum = e0 + e1 + e2 + e3;
        aw[tid][0] = e0 / ssum; aw[tid][1] = e1 / ssum;
        aw[tid][2] = e2 / ssum; aw[tid][3] = e3 / ssum;
    }
    __syncthreads();
    for (int c = tid; c < CDIM; c += 256) {
        int h2 = c >> 6;
        float o = 0.f;
#pragma unroll
        for (int p = 0; p < 4; p++)
            o += aw[h2][p] * vbuf[((size_t)m * PD + p) * CDIM + c];
        obuf[(size_t)m * CDIM + c] = o;
    }
}

// ---------------- host side ----------------------------------------------
static void launch_f32(const float* A, const float* A2, const float* B, float* C,
                       int M, int N, int K, int epi,
                       const float* bias, const float* res) {
    GArgs p = {};
    p.A = A; p.A2 = A2; p.B = B; p.C = C;
    p.M = M; p.N = N; p.K = K; p.lda = K; p.ldb = N; p.ldc = N;
    p.cnt = nullptr; p.cntMul = 1; p.gidx = nullptr; p.gmode = 0;
    p.epi = epi; p.bias = bias; p.res = res;
    dim3 grid(N / 128, (M + 127) / 128);
    gemm_k<<<grid, 256>>>(p);
}

static void launch_bt(const float* A, const float* A2, const float* B, float* C,
                      int M, int N, int K, int lda, int ldb, int ldc,
                      const int* cnt, int cntMul, const int* gidx, int gmode,
                      int epi, const float* mul, const float* gate, float* outAdd,
                      size_t sA, size_t sB, size_t sC, size_t sMul, size_t sList,
                      int zc) {
    GArgs p = {};
    p.A = A; p.A2 = A2; p.B = B; p.C = C;
    p.M = M; p.N = N; p.K = K; p.lda = lda; p.ldb = ldb; p.ldc = ldc;
    p.cnt = cnt; p.cntMul = cntMul; p.gidx = gidx; p.gmode = gmode;
    p.epi = epi; p.mul = mul; p.gate = gate; p.outAdd = outAdd;
    p.sA = sA; p.sB = sB; p.sC = sC; p.sMul = sMul; p.sList = sList;
    cudaFuncSetAttribute(gemm_tf32_k,
                         cudaFuncAttributeMaxDynamicSharedMemorySize, 75776);
    dim3 grid(N / 128, (M + 127) / 128, zc);
    gemm_tf32_k<<<grid, 256, 75776>>>(p);
}

extern "C" void kernel_launch(void* const* d_in, const int* in_sizes, int n_in,
                              void* d_out, int out_size) {
    const float* x      = (const float*)d_in[0];
    const float* cap    = (const float*)d_in[2];
    const float* ln1w   = (const float*)d_in[3];
    const float* ln1b   = (const float*)d_in[4];
    const float* ln2w   = (const float*)d_in[5];
    const float* ln2b   = (const float*)d_in[6];
    const float* Wr     = (const float*)d_in[7];
    const float* Wk     = (const float*)d_in[8];
    const float* Wv     = (const float*)d_in[9];
    const float* Ww     = (const float*)d_in[10];
    const float* w_bias = (const float*)d_in[11];
    const float* Wo     = (const float*)d_in[12];
    const float* conf_w = (const float*)d_in[13];
    const float* conf_b = (const float*)d_in[14];
    const float* Wa     = (const float*)d_in[17];
    const float* ba     = (const float*)d_in[18];
    const float* Wb     = (const float*)d_in[19];
    const float* ffn_Wr = (const float*)d_in[20];
    const float* ffn_Wk = (const float*)d_in[21];
    const float* ffn_Wv = (const float*)d_in[22];
    const float* tr_Wq  = (const float*)d_in[23];
    const float* tr_Wk  = (const float*)d_in[24];
    const float* tr_Wv  = (const float*)d_in[25];
    const float* tr_Wo  = (const float*)d_in[26];
    float* out = (float*)d_out;

    float* base = nullptr;
    cudaGetSymbolAddress((void**)&base, g_scratch);

    float* xln   = base;
    float* rb    = base + 1 * M4;
    float* kb    = base + 2 * M4;
    float* vb    = base + 3 * M4;
    float* wb    = base + 4 * M4;
    float* state = base + 5 * M4;
    float* xatt  = base + 6 * M4;
    float* hbuf  = base + 7 * M4;
    float* qb2   = base + 8 * M4;     // 2 * M4
    float* gb6   = base + 10 * M4;    // 6 * M4
    float* ob2   = base + 16 * M4;    // 2 * M4
    float* kkb   = base + 18 * M4;    // 6 * M16
    float* pb2   = kkb + 6 * M16;     // 2 * M16
    float* kpb2  = pb2 + 2 * M16;     // 2 * M16
    float* vpb2  = kpb2 + 2 * M16;    // 2 * M16
    float* smallr = vpb2 + 2 * M16;
    int*   cnt  = (int*)smallr;
    int*   list = cnt + 8;
    float* gate = (float*)(list + 8 * BTOK);

    int writeV = (out_size >= (int)(2 * M4)) ? 1 : 0;

    // ---- fp32-exact routing-critical path ----
    ln_k<<<BTOK, 256>>>(x, ln1w, ln1b, xln);
    launch_f32(xln, nullptr, Wr, rb, BTOK, CDIM, CDIM, 0, nullptr, nullptr);
    launch_f32(xln, nullptr, Wk, kb, BTOK, CDIM, CDIM, 0, nullptr, nullptr);
    launch_f32(xln, nullptr, Wv, vb, BTOK, CDIM, CDIM, 0, nullptr, nullptr);
    launch_f32(xln, nullptr, Ww, wb, BTOK, CDIM, CDIM, 1, w_bias, nullptr);
    scan_k<<<32, 512>>>(rb, kb, vb, wb, state);
    launch_f32(state, nullptr, Wo, xatt, BTOK, CDIM, CDIM, 7, nullptr, x);
    ln_k<<<BTOK, 256>>>(xatt, ln2w, ln2b, hbuf);
    zero_cnt_k<<<1, 32>>>(cnt);
    route_k<<<BTOK, 32>>>(hbuf, conf_w, conf_b, Wa, ba, cap, cnt, list, gate);
    outinit_k<<<(int)((M4 + 255) / 256), 256>>>(xatt, vb, out, writeV);

    // ---- batched tf32 tensor-core expert path ----
    // FFN stage 1: kk_e = relu^2(gather(h) @ Wk[e]),  z = 0..5
    launch_bt(hbuf, nullptr, ffn_Wk, kkb, BTOK, FFDIM, CDIM, CDIM, FFDIM, FFDIM,
              cnt, 1, list, 1, 2, nullptr, nullptr, nullptr,
              0, (size_t)CDIM * FFDIM, M16, 0, BTOK, 6);
    // FFN stage 2: g_e = sigmoid(gather(h) @ Wr[e])
    launch_bt(hbuf, nullptr, ffn_Wr, gb6, BTOK, CDIM, CDIM, CDIM, CDIM, CDIM,
              cnt, 1, list, 1, 3, nullptr, nullptr, nullptr,
              0, (size_t)CDIM * CDIM, M4, 0, BTOK, 6);
    // FFN stage 3: out[tok] += gate * g_e * (kk_e @ Wv[e])   (atomic scatter)
    launch_bt(kkb, nullptr, ffn_Wv, out, BTOK, CDIM, FFDIM, FFDIM, CDIM, CDIM,
              cnt, 1, list, 0, 5, gb6, gate, out,
              M16, (size_t)FFDIM * CDIM, 0, M4, BTOK, 6);

    // TR stage 1: q_t = gather(h) @ Wq[t],  z = 0..1 (experts 6,7)
    launch_bt(hbuf, nullptr, tr_Wq, qb2, BTOK, CDIM, CDIM, CDIM, CDIM, CDIM,
              cnt + 6, 1, list + 6 * BTOK, 1, 0, nullptr, nullptr, nullptr,
              0, (size_t)CDIM * CDIM, M4, 0, BTOK, 2);
    // TR stage 2: prefix_t = tanh(concat(h,state) @ Wb)   (Wb shared, sB = 0)
    launch_bt(hbuf, state, Wb, pb2, BTOK, FFDIM, 2 * CDIM, CDIM, FFDIM, FFDIM,
              cnt + 6, 1, list + 6 * BTOK, 2, 4, nullptr, nullptr, nullptr,
              0, 0, M16, 0, BTOK, 2);
    // TR stage 3/4: kp, vp = prefix @ Wk/Wv  (M = 4*cnt compacted rows)
    launch_bt(pb2, nullptr, tr_Wk, kpb2, BTOK * PD, CDIM, CDIM, CDIM, CDIM, CDIM,
              cnt + 6, PD, nullptr, 0, 0, nullptr, nullptr, nullptr,
              M16, (size_t)CDIM * CDIM, M16, 0, 0, 2);
    launch_bt(pb2, nullptr, tr_Wv, vpb2, BTOK * PD, CDIM, CDIM, CDIM, CDIM, CDIM,
              cnt + 6, PD, nullptr, 0, 0, nullptr, nullptr, nullptr,
              M16, (size_t)CDIM * CDIM, M16, 0, 0, 2);
    // softmax cross-attention over P=4, batched over both TR experts
    attn_k<<<dim3(BTOK, 2), 256>>>(qb2, kpb2, vpb2, ob2, cnt + 6);
    // TR stage 5: out[tok] += gate * (o_t @ Wo[t])   (atomic scatter)
    launch_bt(ob2, nullptr, tr_Wo, out, BTOK, CDIM, CDIM, CDIM, CDIM, CDIM,
              cnt + 6, 1, list + 6 * BTOK, 0, 6, nullptr, gate + 6 * BTOK, out,
              M4, (size_t)CDIM * CDIM, 0, 0, BTOK, 2);
}

// round 9
// speedup vs baseline: 3.7948x; 1.4535x over previous
#include <cuda_runtime.h>
#include <math.h>
#include <stdint.h>

// Problem constants
#define BTOK 4096          // B*T
#define CDIM 1024
#define FFDIM 4096
#define EEXP 8
#define NREXP 6
#define HN 16
#define HSD 64
#define PD 4
#define TLEN 2048

#define M4E  4194304ull
#define M16E 16777216ull

static const size_t M4  = (size_t)M4E;
static const size_t M16 = (size_t)M16E;

// ---------------- scratch (static device allocation; no cudaMalloc) -------
__device__ float g_scratch[276955136ull];

// ---------------- shared GEMM argument struct -----------------------------
struct GArgs {
    const float* A;
    const float* A2;
    const float* B;
    float* C;
    int M, N, K, lda, ldb, ldc;
    const int* cnt;      // batched: cnt[z]
    int cntMul;
    const int* gidx;
    int gmode;           // 0 none, 1 gather, 2 concat(A|A2) gather
    int epi;             // 0 plain, 1 sigmoid(+bias), 2 relu^2, 3 sigmoid,
                         // 4 tanh, 5 out+=gate*mul*acc (atomic), 6 out+=gate*acc (atomic),
                         // 7 acc+res
    const float* bias;
    const float* res;
    const float* mul;
    const float* gate;
    float* outAdd;
    size_t sA, sB, sC, sMul, sList;
    const float* Barr[4];   // per-z B pointers (3x kernel)
    int useBarr;
    int epi2, epi2zmin;     // z >= epi2zmin uses epi2 (3x kernel)
};

#define CP_A16(dst, src) \
    asm volatile("cp.async.cg.shared.global [%0], [%1], 16;" :: "r"(dst), "l"(src) : "memory")
#define CP_A4(dst, src) \
    asm volatile("cp.async.ca.shared.global [%0], [%1], 4;" :: "r"(dst), "l"(src) : "memory")
#define CP_COMMIT() asm volatile("cp.async.commit_group;" ::: "memory")
#define CP_WAIT2()  asm volatile("cp.async.wait_group 2;" ::: "memory")

__device__ __forceinline__ uint32_t f2tf32(float x) {
    uint32_t r;
    asm("cvt.rna.tf32.f32 %0, %1;" : "=r"(r) : "f"(x));
    return r;
}

#define MMA_TF32(acc, a0, a1, a2, a3, b0, b1) \
    asm volatile( \
        "mma.sync.aligned.m16n8k8.row.col.f32.tf32.tf32.f32 " \
        "{%0,%1,%2,%3},{%4,%5,%6,%7},{%8,%9},{%0,%1,%2,%3};" \
        : "+f"((acc)[0]), "+f"((acc)[1]), "+f"((acc)[2]), "+f"((acc)[3]) \
        : "r"(a0), "r"(a1), "r"(a2), "r"(a3), "r"(b0), "r"(b1))

// ================= batched tf32 tensor-core GEMM (experts) ================
__global__ __launch_bounds__(256) void gemm_tf32_k(GArgs p) {
    int z = blockIdx.z;
    const float* Ab   = p.A + (size_t)z * p.sA;
    const float* Bb   = p.B + (size_t)z * p.sB;
    float*       Cb   = p.C + (size_t)z * p.sC;
    const int*   gidx = p.gidx ? p.gidx + (size_t)z * p.sList : nullptr;
    const float* gteb = p.gate ? p.gate + (size_t)z * p.sList : nullptr;
    const float* mulb = p.mul  ? p.mul  + (size_t)z * p.sMul  : nullptr;

    int effM = p.M;
    if (p.cnt) {
        int c = p.cnt[z] * p.cntMul;
        effM = c < p.M ? c : p.M;
    }
    int m0 = blockIdx.y * 128, n0 = blockIdx.x * 128;
    if (m0 >= effM) return;

    extern __shared__ float dynsmem[];
    float (*As)[128][20] = (float(*)[128][20])dynsmem;
    float (*Bs)[16][136] = (float(*)[16][136])(dynsmem + 4 * 128 * 20);

    int tid = threadIdx.x;
    int wid = tid >> 5, lane = tid & 31;
    int warpM = wid >> 2, warpN = wid & 3;
    int mBase = warpM * 64, nBase = warpN * 32;
    int lq = lane >> 2, lr = lane & 3;

    int aR  = tid >> 2;
    int aC4 = (tid & 3) << 2;
    int bR = tid >> 5;
    int bC = (tid & 31) << 2;

    int gm0 = m0 + aR, gm1 = m0 + aR + 64;
    int cl0 = gm0 < p.M ? gm0 : p.M - 1;
    int cl1 = gm1 < p.M ? gm1 : p.M - 1;
    int arow0, arow1;
    if (p.gmode == 0) { arow0 = cl0; arow1 = cl1; }
    else {
        arow0 = gidx[cl0]; arow1 = gidx[cl1];
        arow0 = ((unsigned)arow0 < (unsigned)BTOK) ? arow0 : 0;
        arow1 = ((unsigned)arow1 < (unsigned)BTOK) ? arow1 : 0;
    }

    uint32_t aD0 = (uint32_t)__cvta_generic_to_shared(&As[0][aR][aC4]);
    uint32_t aD1 = (uint32_t)__cvta_generic_to_shared(&As[0][aR + 64][aC4]);
    uint32_t bD0 = (uint32_t)__cvta_generic_to_shared(&Bs[0][bR][bC]);
    uint32_t bD1 = (uint32_t)__cvta_generic_to_shared(&Bs[0][bR + 8][bC]);
    const uint32_t aStr = 128 * 20 * 4;
    const uint32_t bStr = 16 * 136 * 4;

    auto issueTile = [&](int t, int buf) {
        int k0 = t << 4;
        const float *s0, *s1;
        if (p.gmode == 2) {
            int col = k0 + aC4;
            s0 = (col < CDIM) ? (Ab + (size_t)arow0 * CDIM + col)
                              : (p.A2 + (size_t)arow0 * CDIM + (col - CDIM));
            s1 = (col < CDIM) ? (Ab + (size_t)arow1 * CDIM + col)
                              : (p.A2 + (size_t)arow1 * CDIM + (col - CDIM));
        } else {
            s0 = Ab + (size_t)arow0 * p.lda + k0 + aC4;
            s1 = Ab + (size_t)arow1 * p.lda + k0 + aC4;
        }
        CP_A16(aD0 + buf * aStr, s0);
        CP_A16(aD1 + buf * aStr, s1);
        CP_A16(bD0 + buf * bStr, Bb + (size_t)(k0 + bR)     * p.ldb + n0 + bC);
        CP_A16(bD1 + buf * bStr, Bb + (size_t)(k0 + bR + 8) * p.ldb + n0 + bC);
        CP_COMMIT();
    };

    float acc[4][4][4];
#pragma unroll
    for (int mt = 0; mt < 4; mt++)
#pragma unroll
        for (int nt = 0; nt < 4; nt++)
#pragma unroll
            for (int r = 0; r < 4; r++) acc[mt][nt][r] = 0.f;

    int nK = p.K >> 4;
    issueTile(0, 0);
    if (nK > 1) issueTile(1, 1); else CP_COMMIT();
    if (nK > 2) issueTile(2, 2); else CP_COMMIT();

    for (int t = 0; t < nK; t++) {
        CP_WAIT2();
        __syncthreads();
        if (t + 3 < nK) issueTile(t + 3, (t + 3) & 3); else CP_COMMIT();

        int cb = t & 3;
#pragma unroll
        for (int ks = 0; ks < 2; ks++) {
            int k0 = ks << 3;
            uint32_t a[4][4], b[4][2];
#pragma unroll
            for (int mt = 0; mt < 4; mt++) {
                int r = mBase + mt * 16 + lq;
                a[mt][0] = __float_as_uint(As[cb][r][k0 + lr]);
                a[mt][1] = __float_as_uint(As[cb][r + 8][k0 + lr]);
                a[mt][2] = __float_as_uint(As[cb][r][k0 + lr + 4]);
                a[mt][3] = __float_as_uint(As[cb][r + 8][k0 + lr + 4]);
            }
#pragma unroll
            for (int nt = 0; nt < 4; nt++) {
                int c = nBase + nt * 8 + lq;
                b[nt][0] = __float_as_uint(Bs[cb][k0 + lr][c]);
                b[nt][1] = __float_as_uint(Bs[cb][k0 + lr + 4][c]);
            }
#pragma unroll
            for (int mt = 0; mt < 4; mt++)
#pragma unroll
                for (int nt = 0; nt < 4; nt++)
                    MMA_TF32(acc[mt][nt], a[mt][0], a[mt][1], a[mt][2], a[mt][3],
                             b[nt][0], b[nt][1]);
        }
    }

#pragma unroll
    for (int mt = 0; mt < 4; mt++) {
#pragma unroll
        for (int half = 0; half < 2; half++) {
            int m = m0 + mBase + mt * 16 + lq + half * 8;
            if (m >= effM) continue;
#pragma unroll
            for (int nt = 0; nt < 4; nt++) {
                int n = n0 + nBase + nt * 8 + 2 * lr;
                float v0 = acc[mt][nt][half * 2 + 0];
                float v1 = acc[mt][nt][half * 2 + 1];
                switch (p.epi) {
                    case 0:
                        Cb[(size_t)m * p.ldc + n]     = v0;
                        Cb[(size_t)m * p.ldc + n + 1] = v1;
                        break;
                    case 2: {
                        float r0 = v0 > 0.f ? v0 : 0.f;
                        float r1 = v1 > 0.f ? v1 : 0.f;
                        Cb[(size_t)m * p.ldc + n]     = r0 * r0;
                        Cb[(size_t)m * p.ldc + n + 1] = r1 * r1;
                    } break;
                    case 3:
                        Cb[(size_t)m * p.ldc + n]     = 1.f / (1.f + expf(-v0));
                        Cb[(size_t)m * p.ldc + n + 1] = 1.f / (1.f + expf(-v1));
                        break;
                    case 4:
                        Cb[(size_t)m * p.ldc + n]     = tanhf(v0);
                        Cb[(size_t)m * p.ldc + n + 1] = tanhf(v1);
                        break;
                    case 5: {
                        int r = gidx[m]; float g = gteb[m];
                        atomicAdd(&p.outAdd[(size_t)r * CDIM + n],
                                  g * mulb[(size_t)m * CDIM + n] * v0);
                        atomicAdd(&p.outAdd[(size_t)r * CDIM + n + 1],
                                  g * mulb[(size_t)m * CDIM + n + 1] * v1);
                    } break;
                    case 6: {
                        int r = gidx[m]; float g = gteb[m];
                        atomicAdd(&p.outAdd[(size_t)r * CDIM + n],     g * v0);
                        atomicAdd(&p.outAdd[(size_t)r * CDIM + n + 1], g * v1);
                    } break;
                }
            }
        }
    }
}

// ======= 3xTF32 tensor-core GEMM (fp32-accurate; routing-critical path) ====
// a = a_hi + a_lo, b = b_hi + b_lo; a*b ~= ah*bh + al*bh + ah*bl (err ~2^-22)
__global__ __launch_bounds__(256) void gemm_3x_k(GArgs p) {
    int z = blockIdx.z;
    const float* Ab = p.A + (size_t)z * p.sA;
    const float* Bb = p.useBarr ? p.Barr[z] : (p.B + (size_t)z * p.sB);
    float*       Cb = p.C + (size_t)z * p.sC;
    int epi = (z >= p.epi2zmin) ? p.epi2 : p.epi;

    int m0 = blockIdx.y * 128, n0 = blockIdx.x * 128;
    if (m0 >= p.M) return;

    extern __shared__ float dynsmem[];
    float (*As)[128][20] = (float(*)[128][20])dynsmem;
    float (*Bs)[16][136] = (float(*)[16][136])(dynsmem + 4 * 128 * 20);

    int tid = threadIdx.x;
    int wid = tid >> 5, lane = tid & 31;
    int warpM = wid >> 2, warpN = wid & 3;
    int mBase = warpM * 64, nBase = warpN * 32;
    int lq = lane >> 2, lr = lane & 3;

    int aR  = tid >> 2;
    int aC4 = (tid & 3) << 2;
    int bR = tid >> 5;
    int bC = (tid & 31) << 2;

    int arow0 = m0 + aR, arow1 = m0 + aR + 64;

    uint32_t aD0 = (uint32_t)__cvta_generic_to_shared(&As[0][aR][aC4]);
    uint32_t aD1 = (uint32_t)__cvta_generic_to_shared(&As[0][aR + 64][aC4]);
    uint32_t bD0 = (uint32_t)__cvta_generic_to_shared(&Bs[0][bR][bC]);
    uint32_t bD1 = (uint32_t)__cvta_generic_to_shared(&Bs[0][bR + 8][bC]);
    const uint32_t aStr = 128 * 20 * 4;
    const uint32_t bStr = 16 * 136 * 4;

    auto issueTile = [&](int t, int buf) {
        int k0 = t << 4;
        CP_A16(aD0 + buf * aStr, Ab + (size_t)arow0 * p.lda + k0 + aC4);
        CP_A16(aD1 + buf * aStr, Ab + (size_t)arow1 * p.lda + k0 + aC4);
        CP_A16(bD0 + buf * bStr, Bb + (size_t)(k0 + bR)     * p.ldb + n0 + bC);
        CP_A16(bD1 + buf * bStr, Bb + (size_t)(k0 + bR + 8) * p.ldb + n0 + bC);
        CP_COMMIT();
    };

    float acc[4][4][4];
#pragma unroll
    for (int mt = 0; mt < 4; mt++)
#pragma unroll
        for (int nt = 0; nt < 4; nt++)
#pragma unroll
            for (int r = 0; r < 4; r++) acc[mt][nt][r] = 0.f;

    int nK = p.K >> 4;
    issueTile(0, 0);
    if (nK > 1) issueTile(1, 1); else CP_COMMIT();
    if (nK > 2) issueTile(2, 2); else CP_COMMIT();

    for (int t = 0; t < nK; t++) {
        CP_WAIT2();
        __syncthreads();
        if (t + 3 < nK) issueTile(t + 3, (t + 3) & 3); else CP_COMMIT();

        int cb = t & 3;
#pragma unroll
        for (int ks = 0; ks < 2; ks++) {
            int k0 = ks << 3;
            uint32_t bh[4][2], bl[4][2];
#pragma unroll
            for (int nt = 0; nt < 4; nt++) {
                int c = nBase + nt * 8 + lq;
                float f0 = Bs[cb][k0 + lr][c];
                float f1 = Bs[cb][k0 + lr + 4][c];
                bh[nt][0] = f2tf32(f0);
                bl[nt][0] = f2tf32(f0 - __uint_as_float(bh[nt][0]));
                bh[nt][1] = f2tf32(f1);
                bl[nt][1] = f2tf32(f1 - __uint_as_float(bh[nt][1]));
            }
#pragma unroll
            for (int mt = 0; mt < 4; mt++) {
                int r = mBase + mt * 16 + lq;
                float f0 = As[cb][r][k0 + lr];
                float f1 = As[cb][r + 8][k0 + lr];
                float f2 = As[cb][r][k0 + lr + 4];
                float f3 = As[cb][r + 8][k0 + lr + 4];
                uint32_t ah0 = f2tf32(f0), ah1 = f2tf32(f1);
                uint32_t ah2 = f2tf32(f2), ah3 = f2tf32(f3);
                uint32_t al0 = f2tf32(f0 - __uint_as_float(ah0));
                uint32_t al1 = f2tf32(f1 - __uint_as_float(ah1));
                uint32_t al2 = f2tf32(f2 - __uint_as_float(ah2));
                uint32_t al3 = f2tf32(f3 - __uint_as_float(ah3));
#pragma unroll
                for (int nt = 0; nt < 4; nt++) {
                    MMA_TF32(acc[mt][nt], ah0, ah1, ah2, ah3, bh[nt][0], bh[nt][1]);
                    MMA_TF32(acc[mt][nt], al0, al1, al2, al3, bh[nt][0], bh[nt][1]);
                    MMA_TF32(acc[mt][nt], ah0, ah1, ah2, ah3, bl[nt][0], bl[nt][1]);
                }
            }
        }
    }

#pragma unroll
    for (int mt = 0; mt < 4; mt++) {
#pragma unroll
        for (int half = 0; half < 2; half++) {
            int m = m0 + mBase + mt * 16 + lq + half * 8;
            if (m >= p.M) continue;
#pragma unroll
            for (int nt = 0; nt < 4; nt++) {
                int n = n0 + nBase + nt * 8 + 2 * lr;
                float v0 = acc[mt][nt][half * 2 + 0];
                float v1 = acc[mt][nt][half * 2 + 1];
                switch (epi) {
                    case 0:
                        Cb[(size_t)m * p.ldc + n]     = v0;
                        Cb[(size_t)m * p.ldc + n + 1] = v1;
                        break;
                    case 1:
                        Cb[(size_t)m * p.ldc + n] =
                            1.f / (1.f + expf(-(v0 + p.bias[n])));
                        Cb[(size_t)m * p.ldc + n + 1] =
                            1.f / (1.f + expf(-(v1 + p.bias[n + 1])));
                        break;
                    case 7:
                        Cb[(size_t)m * p.ldc + n] =
                            v0 + p.res[(size_t)m * p.ldc + n];
                        Cb[(size_t)m * p.ldc + n + 1] =
                            v1 + p.res[(size_t)m * p.ldc + n + 1];
                        break;
                }
            }
        }
    }
}

// ---------------- LayerNorm (one block per row) ---------------------------
__global__ __launch_bounds__(256) void ln_k(const float* __restrict__ x,
                                            const float* __restrict__ w,
                                            const float* __restrict__ b,
                                            float* __restrict__ y) {
    int row = blockIdx.x, tid = threadIdx.x;
    const float* xr = x + (size_t)row * CDIM;
    float v[4], s = 0.f, s2 = 0.f;
#pragma unroll
    for (int i = 0; i < 4; i++) {
        v[i] = xr[tid + 256 * i];
        s += v[i]; s2 += v[i] * v[i];
    }
#pragma unroll
    for (int off = 16; off; off >>= 1) {
        s  += __shfl_xor_sync(0xffffffffu, s, off);
        s2 += __shfl_xor_sync(0xffffffffu, s2, off);
    }
    __shared__ float rs[8], rs2[8];
    int wid = tid >> 5, lane = tid & 31;
    if (lane == 0) { rs[wid] = s; rs2[wid] = s2; }
    __syncthreads();
    if (tid == 0) {
        float S = 0.f, S2 = 0.f;
        for (int i = 0; i < 8; i++) { S += rs[i]; S2 += rs2[i]; }
        rs[0] = S; rs2[0] = S2;
    }
    __syncthreads();
    float mean = rs[0] * (1.f / 1024.f);
    float var  = rs2[0] * (1.f / 1024.f) - mean * mean;
    float inv  = rsqrtf(var + 1e-5f);
#pragma unroll
    for (int i = 0; i < 4; i++) {
        int c = tid + 256 * i;
        y[(size_t)row * CDIM + c] = (v[i] - mean) * inv * w[c] + b[c];
    }
}

// ------- RWKV scan: 128 blocks (32 bh x 4 v-chunks), cp.async ring --------
__global__ __launch_bounds__(128) void scan_k(const float* __restrict__ r,
                                              const float* __restrict__ k,
                                              const float* __restrict__ v,
                                              const float* __restrict__ w,
                                              float* __restrict__ y) {
    int bx = blockIdx.x;
    int bh = bx >> 2, vc = bx & 3;
    int b = bh >> 4, h = bh & 15;
    int tid = threadIdx.x;         // 128
    int vdl = tid >> 3;            // 0..15
    int kg  = tid & 7;             // 0..7
    int vd  = vc * 16 + vdl;

    __shared__ float rs[4][64], ks[4][64], ws[4][64], vs[4][16];

    float S[8];
#pragma unroll
    for (int i = 0; i < 8; i++) S[i] = 0.f;

    size_t base = (size_t)b * TLEN * CDIM + (size_t)h * HSD;

    // per-thread copy roles
    // tid 0..63  : rs[tid], ws[tid]
    // tid 64..127: ks[tid-64], plus vs[tid-64] for tid-64 < 16
    auto issueStep = [&](int t, int buf) {
        size_t off = base + (size_t)t * CDIM;
        if (tid < 64) {
            CP_A4((uint32_t)__cvta_generic_to_shared(&rs[buf][tid]), r + off + tid);
            CP_A4((uint32_t)__cvta_generic_to_shared(&ws[buf][tid]), w + off + tid);
        } else {
            int j = tid - 64;
            CP_A4((uint32_t)__cvta_generic_to_shared(&ks[buf][j]), k + off + j);
            if (j < 16)
                CP_A4((uint32_t)__cvta_generic_to_shared(&vs[buf][j]),
                      v + off + vc * 16 + j);
        }
        CP_COMMIT();
    };

    issueStep(0, 0);
    issueStep(1, 1);
    issueStep(2, 2);

    for (int t = 0; t < TLEN; t++) {
        CP_WAIT2();
        __syncthreads();
        if (t + 3 < TLEN) issueStep(t + 3, (t + 3) & 3); else CP_COMMIT();

        int cb = t & 3;
        float vv = vs[cb][vdl];
        float yp = 0.f;
#pragma unroll
        for (int i = 0; i < 8; i++) {
            int ki = kg * 8 + i;
            S[i] = S[i] * ws[cb][ki] + ks[cb][ki] * vv;
            yp += rs[cb][ki] * S[i];
        }
        yp += __shfl_xor_sync(0xffffffffu, yp, 1);
        yp += __shfl_xor_sync(0xffffffffu, yp, 2);
        yp += __shfl_xor_sync(0xffffffffu, yp, 4);
        if (kg == 0) y[base + (size_t)t * CDIM + vd] = yp;
    }
}

// ---------------- routing: one warp per token ----------------------------
__global__ __launch_bounds__(32) void route_k(const float* __restrict__ h,
                                              const float* __restrict__ conf_w,
                                              const float* __restrict__ conf_b,
                                              const float* __restrict__ Wa,
                                              const float* __restrict__ ba,
                                              const float* __restrict__ cap,
                                              int* cnt, int* list, float* gate) {
    int n = blockIdx.x, lane = threadIdx.x;
    const float* hr = h + (size_t)n * CDIM;
    float pc[8], pa[8];
#pragma unroll
    for (int e = 0; e < 8; e++) { pc[e] = 0.f; pa[e] = 0.f; }
    for (int c = lane; c < CDIM; c += 32) {
        float hv = hr[c];
#pragma unroll
        for (int e = 0; e < 8; e++) {
            pc[e] += hv * conf_w[e * CDIM + c];
            pa[e] += hv * Wa[c * 8 + e];
        }
    }
#pragma unroll
    for (int off = 16; off; off >>= 1)
#pragma unroll
        for (int e = 0; e < 8; e++) {
            pc[e] += __shfl_xor_sync(0xffffffffu, pc[e], off);
            pa[e] += __shfl_xor_sync(0xffffffffu, pa[e], off);
        }
    if (lane == 0) {
        float aff[8], bids[8];
        float mx = -1e30f;
#pragma unroll
        for (int e = 0; e < 8; e++) { aff[e] = pa[e] + ba[e]; mx = fmaxf(mx, aff[e]); }
        float ssum = 0.f, ex[8];
#pragma unroll
        for (int e = 0; e < 8; e++) { ex[e] = expf(aff[e] - mx); ssum += ex[e]; }
#pragma unroll
        for (int e = 0; e < 8; e++) {
            float conf = 1.f / (1.f + expf(-(pc[e] + conf_b[e])));
            bids[e] = conf * cap[e] + ex[e] / ssum;
        }
        int e0 = 0;
        for (int e = 1; e < 8; e++) if (bids[e] > bids[e0]) e0 = e;
        int e1 = -1;
        for (int e = 0; e < 8; e++)
            if (e != e0 && (e1 < 0 || bids[e] > bids[e1])) e1 = e;
        float v0 = bids[e0], v1 = bids[e1];
        float w0e = expf(v0 - v0), w1e = expf(v1 - v0);
        float s = w0e + w1e;
        float w0 = w0e / s, w1 = w1e / s;
        int p0 = atomicAdd(&cnt[e0], 1); list[e0 * BTOK + p0] = n; gate[e0 * BTOK + p0] = w0;
        int p1 = atomicAdd(&cnt[e1], 1); list[e1 * BTOK + p1] = n; gate[e1 * BTOK + p1] = w1;
    }
}

__global__ void zero_cnt_k(int* cnt) { if (threadIdx.x < 8) cnt[threadIdx.x] = 0; }

__global__ __launch_bounds__(256) void outinit_k(const float* __restrict__ xatt,
                                                 const float* __restrict__ v,
                                                 float* __restrict__ out, int writeV) {
    size_t i = (size_t)blockIdx.x * 256 + threadIdx.x;
    if (i < M4E) {
        out[i] = xatt[i];
        if (writeV) out[M4E + i] = v[i];
    }
}

// -------- batched tiny cross-attention over P=4 prefix slots --------------
__global__ __launch_bounds__(256) void attn_k(const float* __restrict__ qb,
                                              const float* __restrict__ kb,
                                              const float* __restrict__ vb,
                                              float* __restrict__ ob,
                                              const int* __restrict__ cnt) {
    int z = blockIdx.y;
    int m = blockIdx.x;
    if (m >= cnt[z]) return;
    const float* qbuf = qb + (size_t)z * M4E;
    const float* kbuf = kb + (size_t)z * M16E;
    const float* vbuf = vb + (size_t)z * M16E;
    float* obuf = ob + (size_t)z * M4E;

    int tid = threadIdx.x;
    __shared__ float sc[16][4], aw[16][4];

    int pair = tid >> 2, sub = tid & 3;
    int hh = pair >> 2, pp = pair & 3;
    const float* q  = qbuf + (size_t)m * CDIM + hh * HSD;
    const float* kp = kbuf + ((size_t)m * PD + pp) * CDIM + hh * HSD;
    float s = 0.f;
    for (int i = sub; i < HSD; i += 4) s += q[i] * kp[i];
    s += __shfl_xor_sync(0xffffffffu, s, 1);
    s += __shfl_xor_sync(0xffffffffu, s, 2);
    if (sub == 0) sc[hh][pp] = s * 0.125f;
    __syncthreads();
    if (tid < 16) {
        float m0 = fmaxf(fmaxf(sc[tid][0], sc[tid][1]), fmaxf(sc[tid][2], sc[tid][3]));
        float e0 = expf(sc[tid][0] - m0), e1 = expf(sc[tid][1] - m0);
        float e2 = expf(sc[tid][2] - m0), e3 = expf(sc[tid][3] - m0);
        float ssum = e0 + e1 + e2 + e3;
        aw[tid][0] = e0 / ssum; aw[tid][1] = e1 / ssum;
        aw[tid][2] = e2 / ssum; aw[tid][3] = e3 / ssum;
    }
    __syncthreads();
    for (int c = tid; c < CDIM; c += 256) {
        int h2 = c >> 6;
        float o = 0.f;
#pragma unroll
        for (int p = 0; p < 4; p++)
            o += aw[h2][p] * vbuf[((size_t)m * PD + p) * CDIM + c];
        obuf[(size_t)m * CDIM + c] = o;
    }
}

// ---------------- host side ----------------------------------------------
static void launch_bt(const float* A, const float* A2, const float* B, float* C,
                      int M, int N, int K, int lda, int ldb, int ldc,
                      const int* cnt, int cntMul, const int* gidx, int gmode,
                      int epi, const float* mul, const float* gate, float* outAdd,
                      size_t sA, size_t sB, size_t sC, size_t sMul, size_t sList,
                      int zc) {
    GArgs p = {};
    p.A = A; p.A2 = A2; p.B = B; p.C = C;
    p.M = M; p.N = N; p.K = K; p.lda = lda; p.ldb = ldb; p.ldc = ldc;
    p.cnt = cnt; p.cntMul = cntMul; p.gidx = gidx; p.gmode = gmode;
    p.epi = epi; p.mul = mul; p.gate = gate; p.outAdd = outAdd;
    p.sA = sA; p.sB = sB; p.sC = sC; p.sMul = sMul; p.sList = sList;
    p.epi2zmin = 99;
    cudaFuncSetAttribute(gemm_tf32_k,
                         cudaFuncAttributeMaxDynamicSharedMemorySize, 75776);
    dim3 grid(N / 128, (M + 127) / 128, zc);
    gemm_tf32_k<<<grid, 256, 75776>>>(p);
}

static void launch_3x(const float* A, const float* B0, const float* B1,
                      const float* B2, const float* B3, float* C,
                      int M, int N, int K, size_t sC,
                      int epi, int epi2, int epi2zmin,
                      const float* bias, const float* res, int zc) {
    GArgs p = {};
    p.A = A; p.C = C;
    p.M = M; p.N = N; p.K = K; p.lda = K; p.ldb = N; p.ldc = N;
    p.epi = epi; p.epi2 = epi2; p.epi2zmin = epi2zmin;
    p.bias = bias; p.res = res;
    p.sA = 0; p.sC = sC;
    p.Barr[0] = B0; p.Barr[1] = B1; p.Barr[2] = B2; p.Barr[3] = B3;
    p.useBarr = 1;
    cudaFuncSetAttribute(gemm_3x_k,
                         cudaFuncAttributeMaxDynamicSharedMemorySize, 75776);
    dim3 grid(N / 128, (M + 127) / 128, zc);
    gemm_3x_k<<<grid, 256, 75776>>>(p);
}

extern "C" void kernel_launch(void* const* d_in, const int* in_sizes, int n_in,
                              void* d_out, int out_size) {
    const float* x      = (const float*)d_in[0];
    const float* cap    = (const float*)d_in[2];
    const float* ln1w   = (const float*)d_in[3];
    const float* ln1b   = (const float*)d_in[4];
    const float* ln2w   = (const float*)d_in[5];
    const float* ln2b   = (const float*)d_in[6];
    const float* Wr     = (const float*)d_in[7];
    const float* Wk     = (const float*)d_in[8];
    const float* Wv     = (const float*)d_in[9];
    const float* Ww     = (const float*)d_in[10];
    const float* w_bias = (const float*)d_in[11];
    const float* Wo     = (const float*)d_in[12];
    const float* conf_w = (const float*)d_in[13];
    const float* conf_b = (const float*)d_in[14];
    const float* Wa     = (const float*)d_in[17];
    const float* ba     = (const float*)d_in[18];
    const float* Wb     = (const float*)d_in[19];
    const float* ffn_Wr = (const float*)d_in[20];
    const float* ffn_Wk = (const float*)d_in[21];
    const float* ffn_Wv = (const float*)d_in[22];
    const float* tr_Wq  = (const float*)d_in[23];
    const float* tr_Wk  = (const float*)d_in[24];
    const float* tr_Wv  = (const float*)d_in[25];
    const float* tr_Wo  = (const float*)d_in[26];
    float* out = (float*)d_out;

    float* base = nullptr;
    cudaGetSymbolAddress((void**)&base, g_scratch);

    float* xln   = base;
    float* rb    = base + 1 * M4;
    float* kb    = base + 2 * M4;
    float* vb    = base + 3 * M4;
    float* wb    = base + 4 * M4;
    float* state = base + 5 * M4;
    float* xatt  = base + 6 * M4;
    float* hbuf  = base + 7 * M4;
    float* qb2   = base + 8 * M4;
    float* gb6   = base + 10 * M4;
    float* ob2   = base + 16 * M4;
    float* kkb   = base + 18 * M4;
    float* pb2   = kkb + 6 * M16;
    float* kpb2  = pb2 + 2 * M16;
    float* vpb2  = kpb2 + 2 * M16;
    float* smallr = vpb2 + 2 * M16;
    int*   cnt  = (int*)smallr;
    int*   list = cnt + 8;
    float* gate = (float*)(list + 8 * BTOK);

    int writeV = (out_size >= (int)(2 * M4)) ? 1 : 0;

    // ---- routing-critical path (3xTF32, fp32-accurate) ----
    ln_k<<<BTOK, 256>>>(x, ln1w, ln1b, xln);
    // r,k,v,w projections in ONE batched launch (outputs rb..wb contiguous)
    launch_3x(xln, Wr, Wk, Wv, Ww, rb, BTOK, CDIM, CDIM, M4,
              0, 1, 3, w_bias, nullptr, 4);
    scan_k<<<128, 128>>>(rb, kb, vb, wb, state);
    // x_after_att = x + state @ Wo
    launch_3x(state, Wo, nullptr, nullptr, nullptr, xatt, BTOK, CDIM, CDIM, 0,
              7, 7, 99, nullptr, x, 1);
    ln_k<<<BTOK, 256>>>(xatt, ln2w, ln2b, hbuf);
    zero_cnt_k<<<1, 32>>>(cnt);
    route_k<<<BTOK, 32>>>(hbuf, conf_w, conf_b, Wa, ba, cap, cnt, list, gate);
    outinit_k<<<(int)((M4 + 255) / 256), 256>>>(xatt, vb, out, writeV);

    // ---- batched tf32 tensor-core expert path ----
    launch_bt(hbuf, nullptr, ffn_Wk, kkb, BTOK, FFDIM, CDIM, CDIM, FFDIM, FFDIM,
              cnt, 1, list, 1, 2, nullptr, nullptr, nullptr,
              0, (size_t)CDIM * FFDIM, M16, 0, BTOK, 6);
    launch_bt(hbuf, nullptr, ffn_Wr, gb6, BTOK, CDIM, CDIM, CDIM, CDIM, CDIM,
              cnt, 1, list, 1, 3, nullptr, nullptr, nullptr,
              0, (size_t)CDIM * CDIM, M4, 0, BTOK, 6);
    launch_bt(kkb, nullptr, ffn_Wv, out, BTOK, CDIM, FFDIM, FFDIM, CDIM, CDIM,
              cnt, 1, list, 0, 5, gb6, gate, out,
              M16, (size_t)FFDIM * CDIM, 0, M4, BTOK, 6);

    launch_bt(hbuf, nullptr, tr_Wq, qb2, BTOK, CDIM, CDIM, CDIM, CDIM, CDIM,
              cnt + 6, 1, list + 6 * BTOK, 1, 0, nullptr, nullptr, nullptr,
              0, (size_t)CDIM * CDIM, M4, 0, BTOK, 2);
    launch_bt(hbuf, state, Wb, pb2, BTOK, FFDIM, 2 * CDIM, CDIM, FFDIM, FFDIM,
              cnt + 6, 1, list + 6 * BTOK, 2, 4, nullptr, nullptr, nullptr,
              0, 0, M16, 0, BTOK, 2);
    launch_bt(pb2, nullptr, tr_Wk, kpb2, BTOK * PD, CDIM, CDIM, CDIM, CDIM, CDIM,
              cnt + 6, PD, nullptr, 0, 0, nullptr, nullptr, nullptr,
              M16, (size_t)CDIM * CDIM, M16, 0, 0, 2);
    launch_bt(pb2, nullptr, tr_Wv, vpb2, BTOK * PD, CDIM, CDIM, CDIM, CDIM, CDIM,
              cnt + 6, PD, nullptr, 0, 0, nullptr, nullptr, nullptr,
              M16, (size_t)CDIM * CDIM, M16, 0, 0, 2);
    attn_k<<<dim3(BTOK, 2), 256>>>(qb2, kpb2, vpb2, ob2, cnt + 6);
    launch_bt(ob2, nullptr, tr_Wo, out, BTOK, CDIM, CDIM, CDIM, CDIM, CDIM,
              cnt + 6, 1, list + 6 * BTOK, 0, 6, nullptr, gate + 6 * BTOK, out,
              M4, (size_t)CDIM * CDIM, 0, 0, BTOK, 2);
}

// round 10
// speedup vs baseline: 3.9073x; 1.0297x over previous
#include <cuda_runtime.h>
#include <math.h>
#include <stdint.h>

// Problem constants
#define BTOK 4096          // B*T
#define CDIM 1024
#define FFDIM 4096
#define EEXP 8
#define NREXP 6
#define HN 16
#define HSD 64
#define PD 4
#define TLEN 2048

#define M4E  4194304ull
#define M16E 16777216ull

static const size_t M4  = (size_t)M4E;
static const size_t M16 = (size_t)M16E;

// ---------------- scratch (static device allocation; no cudaMalloc) -------
__device__ float g_scratch[276955136ull];

#define CP_A16(dst, src) \
    asm volatile("cp.async.cg.shared.global [%0], [%1], 16;" :: "r"(dst), "l"(src) : "memory")
#define CP_A4(dst, src) \
    asm volatile("cp.async.ca.shared.global [%0], [%1], 4;" :: "r"(dst), "l"(src) : "memory")
#define CP_COMMIT() asm volatile("cp.async.commit_group;" ::: "memory")
#define CP_WAIT2()  asm volatile("cp.async.wait_group 2;" ::: "memory")

__device__ __forceinline__ uint32_t f2tf32(float x) {
    uint32_t r;
    asm("cvt.rna.tf32.f32 %0, %1;" : "=r"(r) : "f"(x));
    return r;
}

#define MMA_TF32(acc, a0, a1, a2, a3, b0, b1) \
    asm volatile( \
        "mma.sync.aligned.m16n8k8.row.col.f32.tf32.tf32.f32 " \
        "{%0,%1,%2,%3},{%4,%5,%6,%7},{%8,%9},{%0,%1,%2,%3};" \
        : "+f"((acc)[0]), "+f"((acc)[1]), "+f"((acc)[2]), "+f"((acc)[3]) \
        : "r"(a0), "r"(a1), "r"(a2), "r"(a3), "r"(b0), "r"(b1))

// ---------------- per-z GEMM descriptor -----------------------------------
struct ZD {
    const float* A;
    const float* A2;
    const float* B;
    float* C;
    const float* mul;
    const int* gidx;
    const float* gate;
    int K, lda, ldb, ldc;
    int N, Mz;
    int gmode;           // 0 none, 1 gather, 2 concat(A|A2) gather
    int epi;             // 0 plain, 2 relu^2, 3 sigmoid, 4 tanh,
                         // 5 out+=gate*mul*acc (atomic), 6 out+=gate*acc (atomic)
    int cntIdx;          // -1 dense
    int cntMul;
};

struct BArgs {
    ZD zd[16];
    const int* cnt;
    float* outAdd;
};

// ============ generalized batched tf32 tensor-core GEMM (experts) =========
__global__ __launch_bounds__(256) void gemm_bt_k(BArgs q) {
    ZD p = q.zd[blockIdx.z];

    int effM = p.Mz;
    if (p.cntIdx >= 0) {
        int c = q.cnt[p.cntIdx] * p.cntMul;
        effM = c < p.Mz ? c : p.Mz;
    }
    int m0 = blockIdx.y * 128, n0 = blockIdx.x * 128;
    if (m0 >= effM || n0 >= p.N) return;

    extern __shared__ float dynsmem[];
    float (*As)[128][20] = (float(*)[128][20])dynsmem;
    float (*Bs)[16][136] = (float(*)[16][136])(dynsmem + 4 * 128 * 20);

    int tid = threadIdx.x;
    int wid = tid >> 5, lane = tid & 31;
    int warpM = wid >> 2, warpN = wid & 3;
    int mBase = warpM * 64, nBase = warpN * 32;
    int lq = lane >> 2, lr = lane & 3;

    int aR  = tid >> 2;
    int aC4 = (tid & 3) << 2;
    int bR = tid >> 5;
    int bC = (tid & 31) << 2;

    int gm0 = m0 + aR, gm1 = m0 + aR + 64;
    int cl0 = gm0 < p.Mz ? gm0 : p.Mz - 1;
    int cl1 = gm1 < p.Mz ? gm1 : p.Mz - 1;
    int arow0, arow1;
    if (p.gmode == 0) { arow0 = cl0; arow1 = cl1; }
    else {
        arow0 = p.gidx[cl0]; arow1 = p.gidx[cl1];
        arow0 = ((unsigned)arow0 < (unsigned)BTOK) ? arow0 : 0;
        arow1 = ((unsigned)arow1 < (unsigned)BTOK) ? arow1 : 0;
    }

    uint32_t aD0 = (uint32_t)__cvta_generic_to_shared(&As[0][aR][aC4]);
    uint32_t aD1 = (uint32_t)__cvta_generic_to_shared(&As[0][aR + 64][aC4]);
    uint32_t bD0 = (uint32_t)__cvta_generic_to_shared(&Bs[0][bR][bC]);
    uint32_t bD1 = (uint32_t)__cvta_generic_to_shared(&Bs[0][bR + 8][bC]);
    const uint32_t aStr = 128 * 20 * 4;
    const uint32_t bStr = 16 * 136 * 4;

    auto issueTile = [&](int t, int buf) {
        int k0 = t << 4;
        const float *s0, *s1;
        if (p.gmode == 2) {
            int col = k0 + aC4;
            s0 = (col < CDIM) ? (p.A + (size_t)arow0 * CDIM + col)
                              : (p.A2 + (size_t)arow0 * CDIM + (col - CDIM));
            s1 = (col < CDIM) ? (p.A + (size_t)arow1 * CDIM + col)
                              : (p.A2 + (size_t)arow1 * CDIM + (col - CDIM));
        } else {
            s0 = p.A + (size_t)arow0 * p.lda + k0 + aC4;
            s1 = p.A + (size_t)arow1 * p.lda + k0 + aC4;
        }
        CP_A16(aD0 + buf * aStr, s0);
        CP_A16(aD1 + buf * aStr, s1);
        CP_A16(bD0 + buf * bStr, p.B + (size_t)(k0 + bR)     * p.ldb + n0 + bC);
        CP_A16(bD1 + buf * bStr, p.B + (size_t)(k0 + bR + 8) * p.ldb + n0 + bC);
        CP_COMMIT();
    };

    float acc[4][4][4];
#pragma unroll
    for (int mt = 0; mt < 4; mt++)
#pragma unroll
        for (int nt = 0; nt < 4; nt++)
#pragma unroll
            for (int r = 0; r < 4; r++) acc[mt][nt][r] = 0.f;

    int nK = p.K >> 4;
    issueTile(0, 0);
    if (nK > 1) issueTile(1, 1); else CP_COMMIT();
    if (nK > 2) issueTile(2, 2); else CP_COMMIT();

    for (int t = 0; t < nK; t++) {
        CP_WAIT2();
        __syncthreads();
        if (t + 3 < nK) issueTile(t + 3, (t + 3) & 3); else CP_COMMIT();

        int cb = t & 3;
#pragma unroll
        for (int ks = 0; ks < 2; ks++) {
            int k0 = ks << 3;
            uint32_t a[4][4], b[4][2];
#pragma unroll
            for (int mt = 0; mt < 4; mt++) {
                int r = mBase + mt * 16 + lq;
                a[mt][0] = __float_as_uint(As[cb][r][k0 + lr]);
                a[mt][1] = __float_as_uint(As[cb][r + 8][k0 + lr]);
                a[mt][2] = __float_as_uint(As[cb][r][k0 + lr + 4]);
                a[mt][3] = __float_as_uint(As[cb][r + 8][k0 + lr + 4]);
            }
#pragma unroll
            for (int nt = 0; nt < 4; nt++) {
                int c = nBase + nt * 8 + lq;
                b[nt][0] = __float_as_uint(Bs[cb][k0 + lr][c]);
                b[nt][1] = __float_as_uint(Bs[cb][k0 + lr + 4][c]);
            }
#pragma unroll
            for (int mt = 0; mt < 4; mt++)
#pragma unroll
                for (int nt = 0; nt < 4; nt++)
                    MMA_TF32(acc[mt][nt], a[mt][0], a[mt][1], a[mt][2], a[mt][3],
                             b[nt][0], b[nt][1]);
        }
    }

#pragma unroll
    for (int mt = 0; mt < 4; mt++) {
#pragma unroll
        for (int half = 0; half < 2; half++) {
            int m = m0 + mBase + mt * 16 + lq + half * 8;
            if (m >= effM) continue;
#pragma unroll
            for (int nt = 0; nt < 4; nt++) {
                int n = n0 + nBase + nt * 8 + 2 * lr;
                float v0 = acc[mt][nt][half * 2 + 0];
                float v1 = acc[mt][nt][half * 2 + 1];
                switch (p.epi) {
                    case 0:
                        p.C[(size_t)m * p.ldc + n]     = v0;
                        p.C[(size_t)m * p.ldc + n + 1] = v1;
                        break;
                    case 2: {
                        float r0 = v0 > 0.f ? v0 : 0.f;
                        float r1 = v1 > 0.f ? v1 : 0.f;
                        p.C[(size_t)m * p.ldc + n]     = r0 * r0;
                        p.C[(size_t)m * p.ldc + n + 1] = r1 * r1;
                    } break;
                    case 3:
                        p.C[(size_t)m * p.ldc + n]     = 1.f / (1.f + expf(-v0));
                        p.C[(size_t)m * p.ldc + n + 1] = 1.f / (1.f + expf(-v1));
                        break;
                    case 4:
                        p.C[(size_t)m * p.ldc + n]     = tanhf(v0);
                        p.C[(size_t)m * p.ldc + n + 1] = tanhf(v1);
                        break;
                    case 5: {
                        int r = p.gidx[m]; float g = p.gate[m];
                        atomicAdd(&q.outAdd[(size_t)r * CDIM + n],
                                  g * p.mul[(size_t)m * CDIM + n] * v0);
                        atomicAdd(&q.outAdd[(size_t)r * CDIM + n + 1],
                                  g * p.mul[(size_t)m * CDIM + n + 1] * v1);
                    } break;
                    case 6: {
                        int r = p.gidx[m]; float g = p.gate[m];
                        atomicAdd(&q.outAdd[(size_t)r * CDIM + n],     g * v0);
                        atomicAdd(&q.outAdd[(size_t)r * CDIM + n + 1], g * v1);
                    } break;
                }
            }
        }
    }
}

// ======= 3xTF32 tensor-core GEMM (fp32-accurate; routing-critical path) ====
struct GArgs {
    const float* A;
    float* C;
    int M, N, K, lda, ldb, ldc;
    int epi, epi2, epi2zmin;    // 0 plain, 1 sigmoid(+bias), 7 acc+res
    const float* bias;
    const float* res;
    size_t sC;
    const float* Barr[4];
};

__global__ __launch_bounds__(256) void gemm_3x_k(GArgs p) {
    int z = blockIdx.z;
    const float* Ab = p.A;
    const float* Bb = p.Barr[z];
    float*       Cb = p.C + (size_t)z * p.sC;
    int epi = (z >= p.epi2zmin) ? p.epi2 : p.epi;

    int m0 = blockIdx.y * 128, n0 = blockIdx.x * 128;
    if (m0 >= p.M) return;

    extern __shared__ float dynsmem[];
    float (*As)[128][20] = (float(*)[128][20])dynsmem;
    float (*Bs)[16][136] = (float(*)[16][136])(dynsmem + 4 * 128 * 20);

    int tid = threadIdx.x;
    int wid = tid >> 5, lane = tid & 31;
    int warpM = wid >> 2, warpN = wid & 3;
    int mBase = warpM * 64, nBase = warpN * 32;
    int lq = lane >> 2, lr = lane & 3;

    int aR  = tid >> 2;
    int aC4 = (tid & 3) << 2;
    int bR = tid >> 5;
    int bC = (tid & 31) << 2;

    int arow0 = m0 + aR, arow1 = m0 + aR + 64;

    uint32_t aD0 = (uint32_t)__cvta_generic_to_shared(&As[0][aR][aC4]);
    uint32_t aD1 = (uint32_t)__cvta_generic_to_shared(&As[0][aR + 64][aC4]);
    uint32_t bD0 = (uint32_t)__cvta_generic_to_shared(&Bs[0][bR][bC]);
    uint32_t bD1 = (uint32_t)__cvta_generic_to_shared(&Bs[0][bR + 8][bC]);
    const uint32_t aStr = 128 * 20 * 4;
    const uint32_t bStr = 16 * 136 * 4;

    auto issueTile = [&](int t, int buf) {
        int k0 = t << 4;
        CP_A16(aD0 + buf * aStr, Ab + (size_t)arow0 * p.lda + k0 + aC4);
        CP_A16(aD1 + buf * aStr, Ab + (size_t)arow1 * p.lda + k0 + aC4);
        CP_A16(bD0 + buf * bStr, Bb + (size_t)(k0 + bR)     * p.ldb + n0 + bC);
        CP_A16(bD1 + buf * bStr, Bb + (size_t)(k0 + bR + 8) * p.ldb + n0 + bC);
        CP_COMMIT();
    };

    float acc[4][4][4];
#pragma unroll
    for (int mt = 0; mt < 4; mt++)
#pragma unroll
        for (int nt = 0; nt < 4; nt++)
#pragma unroll
            for (int r = 0; r < 4; r++) acc[mt][nt][r] = 0.f;

    int nK = p.K >> 4;
    issueTile(0, 0);
    if (nK > 1) issueTile(1, 1); else CP_COMMIT();
    if (nK > 2) issueTile(2, 2); else CP_COMMIT();

    for (int t = 0; t < nK; t++) {
        CP_WAIT2();
        __syncthreads();
        if (t + 3 < nK) issueTile(t + 3, (t + 3) & 3); else CP_COMMIT();

        int cb = t & 3;
#pragma unroll
        for (int ks = 0; ks < 2; ks++) {
            int k0 = ks << 3;
            uint32_t bh[4][2], bl[4][2];
#pragma unroll
            for (int nt = 0; nt < 4; nt++) {
                int c = nBase + nt * 8 + lq;
                float f0 = Bs[cb][k0 + lr][c];
                float f1 = Bs[cb][k0 + lr + 4][c];
                bh[nt][0] = f2tf32(f0);
                bl[nt][0] = f2tf32(f0 - __uint_as_float(bh[nt][0]));
                bh[nt][1] = f2tf32(f1);
                bl[nt][1] = f2tf32(f1 - __uint_as_float(bh[nt][1]));
            }
#pragma unroll
            for (int mt = 0; mt < 4; mt++) {
                int r = mBase + mt * 16 + lq;
                float f0 = As[cb][r][k0 + lr];
                float f1 = As[cb][r + 8][k0 + lr];
                float f2 = As[cb][r][k0 + lr + 4];
                float f3 = As[cb][r + 8][k0 + lr + 4];
                uint32_t ah0 = f2tf32(f0), ah1 = f2tf32(f1);
                uint32_t ah2 = f2tf32(f2), ah3 = f2tf32(f3);
                uint32_t al0 = f2tf32(f0 - __uint_as_float(ah0));
                uint32_t al1 = f2tf32(f1 - __uint_as_float(ah1));
                uint32_t al2 = f2tf32(f2 - __uint_as_float(ah2));
                uint32_t al3 = f2tf32(f3 - __uint_as_float(ah3));
#pragma unroll
                for (int nt = 0; nt < 4; nt++) {
                    MMA_TF32(acc[mt][nt], ah0, ah1, ah2, ah3, bh[nt][0], bh[nt][1]);
                    MMA_TF32(acc[mt][nt], al0, al1, al2, al3, bh[nt][0], bh[nt][1]);
                    MMA_TF32(acc[mt][nt], ah0, ah1, ah2, ah3, bl[nt][0], bl[nt][1]);
                }
            }
        }
    }

#pragma unroll
    for (int mt = 0; mt < 4; mt++) {
#pragma unroll
        for (int half = 0; half < 2; half++) {
            int m = m0 + mBase + mt * 16 + lq + half * 8;
            if (m >= p.M) continue;
#pragma unroll
            for (int nt = 0; nt < 4; nt++) {
                int n = n0 + nBase + nt * 8 + 2 * lr;
                float v0 = acc[mt][nt][half * 2 + 0];
                float v1 = acc[mt][nt][half * 2 + 1];
                switch (epi) {
                    case 0:
                        Cb[(size_t)m * p.ldc + n]     = v0;
                        Cb[(size_t)m * p.ldc + n + 1] = v1;
                        break;
                    case 1:
                        Cb[(size_t)m * p.ldc + n] =
                            1.f / (1.f + expf(-(v0 + p.bias[n])));
                        Cb[(size_t)m * p.ldc + n + 1] =
                            1.f / (1.f + expf(-(v1 + p.bias[n + 1])));
                        break;
                    case 7:
                        Cb[(size_t)m * p.ldc + n] =
                            v0 + p.res[(size_t)m * p.ldc + n];
                        Cb[(size_t)m * p.ldc + n + 1] =
                            v1 + p.res[(size_t)m * p.ldc + n + 1];
                        break;
                }
            }
        }
    }
}

// ---------------- LayerNorm (one block per row) ---------------------------
__global__ __launch_bounds__(256) void ln_k(const float* __restrict__ x,
                                            const float* __restrict__ w,
                                            const float* __restrict__ b,
                                            float* __restrict__ y) {
    int row = blockIdx.x, tid = threadIdx.x;
    const float* xr = x + (size_t)row * CDIM;
    float v[4], s = 0.f, s2 = 0.f;
#pragma unroll
    for (int i = 0; i < 4; i++) {
        v[i] = xr[tid + 256 * i];
        s += v[i]; s2 += v[i] * v[i];
    }
#pragma unroll
    for (int off = 16; off; off >>= 1) {
        s  += __shfl_xor_sync(0xffffffffu, s, off);
        s2 += __shfl_xor_sync(0xffffffffu, s2, off);
    }
    __shared__ float rs[8], rs2[8];
    int wid = tid >> 5, lane = tid & 31;
    if (lane == 0) { rs[wid] = s; rs2[wid] = s2; }
    __syncthreads();
    if (tid == 0) {
        float S = 0.f, S2 = 0.f;
        for (int i = 0; i < 8; i++) { S += rs[i]; S2 += rs2[i]; }
        rs[0] = S; rs2[0] = S2;
    }
    __syncthreads();
    float mean = rs[0] * (1.f / 1024.f);
    float var  = rs2[0] * (1.f / 1024.f) - mean * mean;
    float inv  = rsqrtf(var + 1e-5f);
#pragma unroll
    for (int i = 0; i < 4; i++) {
        int c = tid + 256 * i;
        y[(size_t)row * CDIM + c] = (v[i] - mean) * inv * w[c] + b[c];
    }
}

// ------- RWKV scan: 128 blocks (32 bh x 4 v-chunks), cp.async ring --------
__global__ __launch_bounds__(128) void scan_k(const float* __restrict__ r,
                                              const float* __restrict__ k,
                                              const float* __restrict__ v,
                                              const float* __restrict__ w,
                                              float* __restrict__ y) {
    int bx = blockIdx.x;
    int bh = bx >> 2, vc = bx & 3;
    int b = bh >> 4, h = bh & 15;
    int tid = threadIdx.x;         // 128
    int vdl = tid >> 3;            // 0..15
    int kg  = tid & 7;             // 0..7
    int vd  = vc * 16 + vdl;

    __shared__ float rs[4][64], ks[4][64], ws[4][64], vs[4][16];

    float S[8];
#pragma unroll
    for (int i = 0; i < 8; i++) S[i] = 0.f;

    size_t base = (size_t)b * TLEN * CDIM + (size_t)h * HSD;

    auto issueStep = [&](int t, int buf) {
        size_t off = base + (size_t)t * CDIM;
        if (tid < 64) {
            CP_A4((uint32_t)__cvta_generic_to_shared(&rs[buf][tid]), r + off + tid);
            CP_A4((uint32_t)__cvta_generic_to_shared(&ws[buf][tid]), w + off + tid);
        } else {
            int j = tid - 64;
            CP_A4((uint32_t)__cvta_generic_to_shared(&ks[buf][j]), k + off + j);
            if (j < 16)
                CP_A4((uint32_t)__cvta_generic_to_shared(&vs[buf][j]),
                      v + off + vc * 16 + j);
        }
        CP_COMMIT();
    };

    issueStep(0, 0);
    issueStep(1, 1);
    issueStep(2, 2);

    for (int t = 0; t < TLEN; t++) {
        CP_WAIT2();
        __syncthreads();
        if (t + 3 < TLEN) issueStep(t + 3, (t + 3) & 3); else CP_COMMIT();

        int cb = t & 3;
        float vv = vs[cb][vdl];
        float yp = 0.f;
#pragma unroll
        for (int i = 0; i < 8; i++) {
            int ki = kg * 8 + i;
            S[i] = S[i] * ws[cb][ki] + ks[cb][ki] * vv;
            yp += rs[cb][ki] * S[i];
        }
        yp += __shfl_xor_sync(0xffffffffu, yp, 1);
        yp += __shfl_xor_sync(0xffffffffu, yp, 2);
        yp += __shfl_xor_sync(0xffffffffu, yp, 4);
        if (kg == 0) y[base + (size_t)t * CDIM + vd] = yp;
    }
}

// ---------------- routing: one warp per token ----------------------------
__global__ __launch_bounds__(32) void route_k(const float* __restrict__ h,
                                              const float* __restrict__ conf_w,
                                              const float* __restrict__ conf_b,
                                              const float* __restrict__ Wa,
                                              const float* __restrict__ ba,
                                              const float* __restrict__ cap,
                                              int* cnt, int* list, float* gate) {
    int n = blockIdx.x, lane = threadIdx.x;
    const float* hr = h + (size_t)n * CDIM;
    float pc[8], pa[8];
#pragma unroll
    for (int e = 0; e < 8; e++) { pc[e] = 0.f; pa[e] = 0.f; }
    for (int c = lane; c < CDIM; c += 32) {
        float hv = hr[c];
#pragma unroll
        for (int e = 0; e < 8; e++) {
            pc[e] += hv * conf_w[e * CDIM + c];
            pa[e] += hv * Wa[c * 8 + e];
        }
    }
#pragma unroll
    for (int off = 16; off; off >>= 1)
#pragma unroll
        for (int e = 0; e < 8; e++) {
            pc[e] += __shfl_xor_sync(0xffffffffu, pc[e], off);
            pa[e] += __shfl_xor_sync(0xffffffffu, pa[e], off);
        }
    if (lane == 0) {
        float aff[8], bids[8];
        float mx = -1e30f;
#pragma unroll
        for (int e = 0; e < 8; e++) { aff[e] = pa[e] + ba[e]; mx = fmaxf(mx, aff[e]); }
        float ssum = 0.f, ex[8];
#pragma unroll
        for (int e = 0; e < 8; e++) { ex[e] = expf(aff[e] - mx); ssum += ex[e]; }
#pragma unroll
        for (int e = 0; e < 8; e++) {
            float conf = 1.f / (1.f + expf(-(pc[e] + conf_b[e])));
            bids[e] = conf * cap[e] + ex[e] / ssum;
        }
        int e0 = 0;
        for (int e = 1; e < 8; e++) if (bids[e] > bids[e0]) e0 = e;
        int e1 = -1;
        for (int e = 0; e < 8; e++)
            if (e != e0 && (e1 < 0 || bids[e] > bids[e1])) e1 = e;
        float v0 = bids[e0], v1 = bids[e1];
        float w0e = expf(v0 - v0), w1e = expf(v1 - v0);
        float s = w0e + w1e;
        float w0 = w0e / s, w1 = w1e / s;
        int p0 = atomicAdd(&cnt[e0], 1); list[e0 * BTOK + p0] = n; gate[e0 * BTOK + p0] = w0;
        int p1 = atomicAdd(&cnt[e1], 1); list[e1 * BTOK + p1] = n; gate[e1 * BTOK + p1] = w1;
    }
}

__global__ void zero_cnt_k(int* cnt) { if (threadIdx.x < 8) cnt[threadIdx.x] = 0; }

__global__ __launch_bounds__(256) void outinit_k(const float* __restrict__ xatt,
                                                 const float* __restrict__ v,
                                                 float* __restrict__ out, int writeV) {
    size_t i = (size_t)blockIdx.x * 256 + threadIdx.x;
    if (i < M4E) {
        out[i] = xatt[i];
        if (writeV) out[M4E + i] = v[i];
    }
}

// -------- batched tiny cross-attention over P=4 prefix slots --------------
__global__ __launch_bounds__(256) void attn_k(const float* __restrict__ qb,
                                              const float* __restrict__ kb,
                                              const float* __restrict__ vb,
                                              float* __restrict__ ob,
                                              const int* __restrict__ cnt) {
    int z = blockIdx.y;
    int m = blockIdx.x;
    if (m >= cnt[z]) return;
    const float* qbuf = qb + (size_t)z * M4E;
    const float* kbuf = kb + (size_t)z * M16E;
    const float* vbuf = vb + (size_t)z * M16E;
    float* obuf = ob + (size_t)z * M4E;

    int tid = threadIdx.x;
    __shared__ float sc[16][4], aw[16][4];

    int pair = tid >> 2, sub = tid & 3;
    int hh = pair >> 2, pp = pair & 3;
    const float* q  = qbuf + (size_t)m * CDIM + hh * HSD;
    const float* kp = kbuf + ((size_t)m * PD + pp) * CDIM + hh * HSD;
    float s = 0.f;
    for (int i = sub; i < HSD; i += 4) s += q[i] * kp[i];
    s += __shfl_xor_sync(0xffffffffu, s, 1);
    s += __shfl_xor_sync(0xffffffffu, s, 2);
    if (sub == 0) sc[hh][pp] = s * 0.125f;
    __syncthreads();
    if (tid < 16) {
        float m0 = fmaxf(fmaxf(sc[tid][0], sc[tid][1]), fmaxf(sc[tid][2], sc[tid][3]));
        float e0 = expf(sc[tid][0] - m0), e1 = expf(sc[tid][1] - m0);
        float e2 = expf(sc[tid][2] - m0), e3 = expf(sc[tid][3] - m0);
        float ssum = e0 + e1 + e2 + e3;
        aw[tid][0] = e0 / ssum; aw[tid][1] = e1 / ssum;
        aw[tid][2] = e2 / ssum; aw[tid][3] = e3 / ssum;
    }
    __syncthreads();
    for (int c = tid; c < CDIM; c += 256) {
        int h2 = c >> 6;
        float o = 0.f;
#pragma unroll
        for (int p = 0; p < 4; p++)
            o += aw[h2][p] * vbuf[((size_t)m * PD + p) * CDIM + c];
        obuf[(size_t)m * CDIM + c] = o;
    }
}

// ---------------- host side ----------------------------------------------
static void set_zd(ZD& z, const float* A, const float* A2, const float* B, float* C,
                   const float* mul, const int* gidx, const float* gate,
                   int K, int lda, int ldb, int ldc, int N, int Mz,
                   int gmode, int epi, int cntIdx, int cntMul) {
    z.A = A; z.A2 = A2; z.B = B; z.C = C; z.mul = mul; z.gidx = gidx; z.gate = gate;
    z.K = K; z.lda = lda; z.ldb = ldb; z.ldc = ldc; z.N = N; z.Mz = Mz;
    z.gmode = gmode; z.epi = epi; z.cntIdx = cntIdx; z.cntMul = cntMul;
}

static void launch_3x(const float* A, const float* B0, const float* B1,
                      const float* B2, const float* B3, float* C,
                      int M, int N, int K, size_t sC,
                      int epi, int epi2, int epi2zmin,
                      const float* bias, const float* res, int zc) {
    GArgs p = {};
    p.A = A; p.C = C;
    p.M = M; p.N = N; p.K = K; p.lda = K; p.ldb = N; p.ldc = N;
    p.epi = epi; p.epi2 = epi2; p.epi2zmin = epi2zmin;
    p.bias = bias; p.res = res;
    p.sC = sC;
    p.Barr[0] = B0; p.Barr[1] = B1; p.Barr[2] = B2; p.Barr[3] = B3;
    cudaFuncSetAttribute(gemm_3x_k,
                         cudaFuncAttributeMaxDynamicSharedMemorySize, 75776);
    dim3 grid(N / 128, (M + 127) / 128, zc);
    gemm_3x_k<<<grid, 256, 75776>>>(p);
}

extern "C" void kernel_launch(void* const* d_in, const int* in_sizes, int n_in,
                              void* d_out, int out_size) {
    const float* x      = (const float*)d_in[0];
    const float* cap    = (const float*)d_in[2];
    const float* ln1w   = (const float*)d_in[3];
    const float* ln1b   = (const float*)d_in[4];
    const float* ln2w   = (const float*)d_in[5];
    const float* ln2b   = (const float*)d_in[6];
    const float* Wr     = (const float*)d_in[7];
    const float* Wk     = (const float*)d_in[8];
    const float* Wv     = (const float*)d_in[9];
    const float* Ww     = (const float*)d_in[10];
    const float* w_bias = (const float*)d_in[11];
    const float* Wo     = (const float*)d_in[12];
    const float* conf_w = (const float*)d_in[13];
    const float* conf_b = (const float*)d_in[14];
    const float* Wa     = (const float*)d_in[17];
    const float* ba     = (const float*)d_in[18];
    const float* Wb     = (const float*)d_in[19];
    const float* ffn_Wr = (const float*)d_in[20];
    const float* ffn_Wk = (const float*)d_in[21];
    const float* ffn_Wv = (const float*)d_in[22];
    const float* tr_Wq  = (const float*)d_in[23];
    const float* tr_Wk  = (const float*)d_in[24];
    const float* tr_Wv  = (const float*)d_in[25];
    const float* tr_Wo  = (const float*)d_in[26];
    float* out = (float*)d_out;

    float* base = nullptr;
    cudaGetSymbolAddress((void**)&base, g_scratch);

    float* xln   = base;
    float* rb    = base + 1 * M4;
    float* kb    = base + 2 * M4;
    float* vb    = base + 3 * M4;
    float* wb    = base + 4 * M4;
    float* state = base + 5 * M4;
    float* xatt  = base + 6 * M4;
    float* hbuf  = base + 7 * M4;
    float* qb2   = base + 8 * M4;
    float* gb6   = base + 10 * M4;
    float* ob2   = base + 16 * M4;
    float* kkb   = base + 18 * M4;
    float* pb2   = kkb + 6 * M16;
    float* kpb2  = pb2 + 2 * M16;
    float* vpb2  = kpb2 + 2 * M16;
    float* smallr = vpb2 + 2 * M16;
    int*   cnt  = (int*)smallr;
    int*   list = cnt + 8;
    float* gate = (float*)(list + 8 * BTOK);

    int writeV = (out_size >= (int)(2 * M4)) ? 1 : 0;

    // ---- routing-critical path (3xTF32, fp32-accurate) ----
    ln_k<<<BTOK, 256>>>(x, ln1w, ln1b, xln);
    launch_3x(xln, Wr, Wk, Wv, Ww, rb, BTOK, CDIM, CDIM, M4,
              0, 1, 3, w_bias, nullptr, 4);
    scan_k<<<128, 128>>>(rb, kb, vb, wb, state);
    launch_3x(state, Wo, nullptr, nullptr, nullptr, xatt, BTOK, CDIM, CDIM, 0,
              7, 7, 99, nullptr, x, 1);
    ln_k<<<BTOK, 256>>>(xatt, ln2w, ln2b, hbuf);
    zero_cnt_k<<<1, 32>>>(cnt);
    route_k<<<BTOK, 32>>>(hbuf, conf_w, conf_b, Wa, ba, cap, cnt, list, gate);
    outinit_k<<<(int)((M4 + 255) / 256), 256>>>(xatt, vb, out, writeV);

    cudaFuncSetAttribute(gemm_bt_k,
                         cudaFuncAttributeMaxDynamicSharedMemorySize, 75776);

    // ---- BIG1 (z=16): everything depending only on h/state/routing ----
    {
        BArgs q = {};
        q.cnt = cnt; q.outAdd = out;
        for (int e = 0; e < 6; e++)
            set_zd(q.zd[e], hbuf, nullptr, ffn_Wk + (size_t)e * CDIM * FFDIM,
                   kkb + (size_t)e * M16, nullptr, list + e * BTOK, nullptr,
                   CDIM, CDIM, FFDIM, FFDIM, FFDIM, BTOK, 1, 2, e, 1);
        for (int t = 0; t < 2; t++)
            set_zd(q.zd[6 + t], hbuf, state, Wb,
                   pb2 + (size_t)t * M16, nullptr, list + (6 + t) * BTOK, nullptr,
                   2 * CDIM, CDIM, FFDIM, FFDIM, FFDIM, BTOK, 2, 4, 6 + t, 1);
        for (int e = 0; e < 6; e++)
            set_zd(q.zd[8 + e], hbuf, nullptr, ffn_Wr + (size_t)e * CDIM * CDIM,
                   gb6 + (size_t)e * M4, nullptr, list + e * BTOK, nullptr,
                   CDIM, CDIM, CDIM, CDIM, CDIM, BTOK, 1, 3, e, 1);
        for (int t = 0; t < 2; t++)
            set_zd(q.zd[14 + t], hbuf, nullptr, tr_Wq + (size_t)t * CDIM * CDIM,
                   qb2 + (size_t)t * M4, nullptr, list + (6 + t) * BTOK, nullptr,
                   CDIM, CDIM, CDIM, CDIM, CDIM, BTOK, 1, 0, 6 + t, 1);
        gemm_bt_k<<<dim3(32, 32, 16), 256, 75776>>>(q);
    }

    // ---- MID (z=10): kp/vp (dep prefix) + FFN-Wv scatter (dep kk,gb) ----
    {
        BArgs q = {};
        q.cnt = cnt; q.outAdd = out;
        for (int t = 0; t < 2; t++) {
            set_zd(q.zd[t], pb2 + (size_t)t * M16, nullptr,
                   tr_Wk + (size_t)t * CDIM * CDIM, kpb2 + (size_t)t * M16,
                   nullptr, nullptr, nullptr,
                   CDIM, CDIM, CDIM, CDIM, CDIM, BTOK * PD, 0, 0, 6 + t, PD);
            set_zd(q.zd[2 + t], pb2 + (size_t)t * M16, nullptr,
                   tr_Wv + (size_t)t * CDIM * CDIM, vpb2 + (size_t)t * M16,
                   nullptr, nullptr, nullptr,
                   CDIM, CDIM, CDIM, CDIM, CDIM, BTOK * PD, 0, 0, 6 + t, PD);
        }
        for (int e = 0; e < 6; e++)
            set_zd(q.zd[4 + e], kkb + (size_t)e * M16, nullptr,
                   ffn_Wv + (size_t)e * FFDIM * CDIM, nullptr,
                   gb6 + (size_t)e * M4, list + e * BTOK, gate + e * BTOK,
                   FFDIM, FFDIM, CDIM, CDIM, CDIM, BTOK, 0, 5, e, 1);
        gemm_bt_k<<<dim3(8, 128, 10), 256, 75776>>>(q);
    }

    // ---- attention over P=4 ----
    attn_k<<<dim3(BTOK, 2), 256>>>(qb2, kpb2, vpb2, ob2, cnt + 6);

    // ---- WO (z=2): out += gate * (o_t @ tr_Wo[t]) ----
    {
        BArgs q = {};
        q.cnt = cnt; q.outAdd = out;
        for (int t = 0; t < 2; t++)
            set_zd(q.zd[t], ob2 + (size_t)t * M4, nullptr,
                   tr_Wo + (size_t)t * CDIM * CDIM, nullptr,
                   nullptr, list + (6 + t) * BTOK, gate + (6 + t) * BTOK,
                   CDIM, CDIM, CDIM, CDIM, CDIM, BTOK, 0, 6, 6 + t, 1);
        gemm_bt_k<<<dim3(8, 32, 2), 256, 75776>>>(q);
    }
}